// round 2
// baseline (speedup 1.0000x reference)
#include <cuda_runtime.h>
#include <math.h>

#define B_    8
#define L_    512
#define D_    1024
#define H_    16
#define DKH_  64
#define F_    4096
#define NL_   6
#define ROWS_ (B_*L_)          /* 4096 */
#define NST_  (ROWS_*D_)       /* 4194304 */

// ---------------- scratch (device globals; no allocation allowed) ------------
__device__ float g_state[NST_];
__device__ float g_prev [NST_];
__device__ float g_xn   [NST_];
__device__ float g_q    [NST_];
__device__ float g_kb   [NST_];
__device__ float g_v    [NST_];
__device__ float g_ctx  [NST_];
__device__ float g_att  [(size_t)B_*H_*L_*L_];   // 33.5M floats
__device__ float g_h    [(size_t)ROWS_*F_];      // 16.8M floats
__device__ float g_hp [ROWS_];
__device__ float g_rem[ROWS_];
__device__ float g_nup[ROWS_];
__device__ float g_uw [ROWS_];

// ---------------- small elementwise kernels ---------------------------------
__global__ void embed_init(const int* __restrict__ X, const float* __restrict__ emb) {
    int idx = blockIdx.x * 256 + threadIdx.x;   // < NST_
    int row = idx >> 10;
    int d   = idx & 1023;
    g_state[idx] = emb[(size_t)X[row] * 1024 + d];
    g_prev[idx]  = 0.f;
}

__global__ void zero_act() {
    int i = blockIdx.x * 256 + threadIdx.x;
    if (i < ROWS_) { g_hp[i] = 0.f; g_rem[i] = 0.f; g_nup[i] = 0.f; }
}

// time signal: channels=1024, num_timescales=512, inv_t[i]=exp(-i*ln(1e4)/511)
__global__ void add_time_pos(int t) {
    const float NEG_LOG_INC = -0.018024149455921103f;  // -ln(10000)/511
    int idx = blockIdx.x * 256 + threadIdx.x;
    int d = idx & 1023;
    int l = (idx >> 10) & 511;
    int i = d & 511;
    float invt = expf((float)i * NEG_LOG_INC);
    float a1 = (float)l * invt;
    float a2 = (float)t * invt;
    float v = (d < 512) ? (sinf(a1) + sinf(a2)) : (cosf(a1) + cosf(a2));
    g_state[idx] += v;
}

// ACT halting: one warp per (b,l) row
__global__ void act_halt(const float* __restrict__ p_w, const float* __restrict__ p_b) {
    int warp = threadIdx.x >> 5, lane = threadIdx.x & 31;
    int row  = blockIdx.x * 8 + warp;
    const float* x = g_state + (size_t)row * 1024;
    float s = 0.f;
    #pragma unroll
    for (int i = 0; i < 32; i++) s += x[lane + 32*i] * p_w[lane + 32*i];
    #pragma unroll
    for (int o = 16; o; o >>= 1) s += __shfl_xor_sync(0xffffffffu, s, o);
    if (lane == 0) {
        float p   = 1.f / (1.f + expf(-(s + p_b[0])));
        float hp  = g_hp[row], rem = g_rem[row], nup = g_nup[row];
        float still = (hp < 1.0f) ? 1.f : 0.f;
        float add   = hp + p * still;
        float nh    = ((add > 0.9f) ? 1.f : 0.f) * still;
        still       = ((add <= 0.9f) ? 1.f : 0.f) * still;
        hp  += p * still;
        rem += nh * (1.f - hp);
        hp  += nh * rem;
        nup += still + nh;
        g_hp[row] = hp; g_rem[row] = rem; g_nup[row] = nup;
        g_uw[row] = p * still + nh * rem;
    }
}

// layernorm with ddof=1 std, eps added to std
__global__ __launch_bounds__(256) void layernorm_k(
    const float* __restrict__ in, float* __restrict__ out,
    const float* __restrict__ g, const float* __restrict__ b)
{
    __shared__ float sh1[8], sh2[8];
    int row = blockIdx.x;
    int tid = threadIdx.x;
    const float* x = in + (size_t)row * 1024;
    float v[4];
    #pragma unroll
    for (int j = 0; j < 4; j++) v[j] = x[tid + 256*j];
    float s = v[0] + v[1] + v[2] + v[3];
    #pragma unroll
    for (int o = 16; o; o >>= 1) s += __shfl_xor_sync(0xffffffffu, s, o);
    if ((tid & 31) == 0) sh1[tid >> 5] = s;
    __syncthreads();
    float tot = 0.f;
    #pragma unroll
    for (int w = 0; w < 8; w++) tot += sh1[w];
    float mu = tot * (1.f / 1024.f);
    float q = 0.f;
    #pragma unroll
    for (int j = 0; j < 4; j++) { float d = v[j] - mu; q += d * d; }
    #pragma unroll
    for (int o = 16; o; o >>= 1) q += __shfl_xor_sync(0xffffffffu, q, o);
    if ((tid & 31) == 0) sh2[tid >> 5] = q;
    __syncthreads();
    float qt = 0.f;
    #pragma unroll
    for (int w = 0; w < 8; w++) qt += sh2[w];
    float sd  = sqrtf(qt / 1023.f);
    float inv = 1.f / (sd + 1e-6f);
    #pragma unroll
    for (int j = 0; j < 4; j++) {
        int d = tid + 256*j;
        out[(size_t)row * 1024 + d] = g[d] * (v[j] - mu) * inv + b[d];
    }
}

__global__ void prev_update() {
    int idx = blockIdx.x * 256 + threadIdx.x;
    int row = idx >> 10;
    float u = g_uw[row];
    g_prev[idx] = g_state[idx] * u + g_prev[idx] * (1.f - u);
}

// ---------------- SGEMM: 128x128 tile, 8x8/thread, BK=16 ---------------------
// EPI 0: C = alpha * (A@B);  EPI 1: C = A@B + res
template<int EPI>
__global__ __launch_bounds__(256) void sgemm128(
    const float* __restrict__ A, const float* __restrict__ B, float* __restrict__ C,
    const float* __restrict__ res, float alpha, int M, int N, int K)
{
    __shared__ float As[16][128];
    __shared__ float Bs[16][128];
    int tid = threadIdx.x;
    int bm = blockIdx.y * 128, bn = blockIdx.x * 128;
    int ar = tid >> 1, ac = (tid & 1) * 8;
    int br = tid >> 4, bc = (tid & 15) * 8;
    const float* Aptr = A + (size_t)(bm + ar) * K + ac;
    const float* Bptr = B + (size_t)br * N + bn + bc;
    int ty8 = (tid >> 4) * 8, tx8 = (tid & 15) * 8;
    float acc[8][8];
    #pragma unroll
    for (int i = 0; i < 8; i++)
        #pragma unroll
        for (int j = 0; j < 8; j++) acc[i][j] = 0.f;

    for (int k0 = 0; k0 < K; k0 += 16) {
        float4 a0 = *(const float4*)(Aptr + k0);
        float4 a1 = *(const float4*)(Aptr + k0 + 4);
        As[ac+0][ar] = a0.x; As[ac+1][ar] = a0.y; As[ac+2][ar] = a0.z; As[ac+3][ar] = a0.w;
        As[ac+4][ar] = a1.x; As[ac+5][ar] = a1.y; As[ac+6][ar] = a1.z; As[ac+7][ar] = a1.w;
        *(float4*)&Bs[br][bc]     = *(const float4*)(Bptr + (size_t)k0 * N);
        *(float4*)&Bs[br][bc + 4] = *(const float4*)(Bptr + (size_t)k0 * N + 4);
        __syncthreads();
        #pragma unroll
        for (int k = 0; k < 16; k++) {
            float4 qa0 = *(const float4*)&As[k][ty8];
            float4 qa1 = *(const float4*)&As[k][ty8 + 4];
            float4 qb0 = *(const float4*)&Bs[k][tx8];
            float4 qb1 = *(const float4*)&Bs[k][tx8 + 4];
            float a[8] = {qa0.x,qa0.y,qa0.z,qa0.w,qa1.x,qa1.y,qa1.z,qa1.w};
            float b[8] = {qb0.x,qb0.y,qb0.z,qb0.w,qb1.x,qb1.y,qb1.z,qb1.w};
            #pragma unroll
            for (int i = 0; i < 8; i++)
                #pragma unroll
                for (int j = 0; j < 8; j++) acc[i][j] += a[i] * b[j];
        }
        __syncthreads();
    }
    #pragma unroll
    for (int i = 0; i < 8; i++) {
        int row = bm + ty8 + i;
        float* cp = C + (size_t)row * N + bn + tx8;
        float v[8];
        #pragma unroll
        for (int j = 0; j < 8; j++) v[j] = acc[i][j];
        if (EPI == 0) {
            #pragma unroll
            for (int j = 0; j < 8; j++) v[j] *= alpha;
        } else {
            const float* rp = res + (size_t)row * N + bn + tx8;
            #pragma unroll
            for (int j = 0; j < 8; j++) v[j] += rp[j];
        }
        *(float4*)cp       = make_float4(v[0], v[1], v[2], v[3]);
        *(float4*)(cp + 4) = make_float4(v[4], v[5], v[6], v[7]);
    }
}

// ---------------- implicit-GEMM conv1d(width=3, pad=1) ----------------------
// A_virtual[(b*L+l), w*Din+c] = Xsrc[b, l+w-1, c] (0 outside). B is (3*Din, N).
// EPI 0: C = relu(acc + bias);  EPI 1: C = acc + bias + res
template<int DSHIFT, int EPI>
__global__ __launch_bounds__(256) void convgemm128(
    const float* __restrict__ Xsrc, const float* __restrict__ B, float* __restrict__ C,
    const float* __restrict__ res, const float* __restrict__ bias, int N, int K)
{
    const int DIN = 1 << DSHIFT;
    __shared__ float As[16][128];
    __shared__ float Bs[16][128];
    int tid = threadIdx.x;
    int bm = blockIdx.y * 128, bn = blockIdx.x * 128;
    int ar = tid >> 1, ac = (tid & 1) * 8;
    int br = tid >> 4, bc = (tid & 15) * 8;
    int r  = bm + ar;
    int bb = r >> 9;
    int l  = r & 511;
    const float* Bptr = B + (size_t)br * N + bn + bc;
    int ty8 = (tid >> 4) * 8, tx8 = (tid & 15) * 8;
    float acc[8][8];
    #pragma unroll
    for (int i = 0; i < 8; i++)
        #pragma unroll
        for (int j = 0; j < 8; j++) acc[i][j] = 0.f;

    for (int k0 = 0; k0 < K; k0 += 16) {
        int kk = k0 + ac;                 // multiple of 8, no Din-boundary straddle
        int w  = kk >> DSHIFT;
        int c  = kk & (DIN - 1);
        int l2 = l + w - 1;
        float4 a0, a1;
        if ((unsigned)l2 < 512u) {
            const float* p = Xsrc + (((size_t)(bb * 512 + l2)) << DSHIFT) + c;
            a0 = *(const float4*)p;
            a1 = *(const float4*)(p + 4);
        } else {
            a0 = make_float4(0.f,0.f,0.f,0.f);
            a1 = make_float4(0.f,0.f,0.f,0.f);
        }
        As[ac+0][ar] = a0.x; As[ac+1][ar] = a0.y; As[ac+2][ar] = a0.z; As[ac+3][ar] = a0.w;
        As[ac+4][ar] = a1.x; As[ac+5][ar] = a1.y; As[ac+6][ar] = a1.z; As[ac+7][ar] = a1.w;
        *(float4*)&Bs[br][bc]     = *(const float4*)(Bptr + (size_t)k0 * N);
        *(float4*)&Bs[br][bc + 4] = *(const float4*)(Bptr + (size_t)k0 * N + 4);
        __syncthreads();
        #pragma unroll
        for (int k = 0; k < 16; k++) {
            float4 qa0 = *(const float4*)&As[k][ty8];
            float4 qa1 = *(const float4*)&As[k][ty8 + 4];
            float4 qb0 = *(const float4*)&Bs[k][tx8];
            float4 qb1 = *(const float4*)&Bs[k][tx8 + 4];
            float a[8] = {qa0.x,qa0.y,qa0.z,qa0.w,qa1.x,qa1.y,qa1.z,qa1.w};
            float b[8] = {qb0.x,qb0.y,qb0.z,qb0.w,qb1.x,qb1.y,qb1.z,qb1.w};
            #pragma unroll
            for (int i = 0; i < 8; i++)
                #pragma unroll
                for (int j = 0; j < 8; j++) acc[i][j] += a[i] * b[j];
        }
        __syncthreads();
    }
    #pragma unroll
    for (int i = 0; i < 8; i++) {
        int row = bm + ty8 + i;
        float* cp = C + (size_t)row * N + bn + tx8;
        float v[8];
        #pragma unroll
        for (int j = 0; j < 8; j++) {
            float val = acc[i][j] + bias[bn + tx8 + j];
            if (EPI == 0) val = fmaxf(val, 0.f);
            v[j] = val;
        }
        if (EPI == 1) {
            const float* rp = res + (size_t)row * N + bn + tx8;
            #pragma unroll
            for (int j = 0; j < 8; j++) v[j] += rp[j];
        }
        *(float4*)cp       = make_float4(v[0], v[1], v[2], v[3]);
        *(float4*)(cp + 4) = make_float4(v[4], v[5], v[6], v[7]);
    }
}

// ---------------- attention ---------------------------------------------------
// logits[b,h,q,k] = sum_d q[b,q,h,d] * k[b,k,h,d]  (scale folded into q)
__global__ __launch_bounds__(256) void attn_logits(
    const float* __restrict__ q, const float* __restrict__ kb, float* __restrict__ att)
{
    __shared__ float Qs[64][64];
    __shared__ float Ks[64][64];
    int bh = blockIdx.z;
    int b = bh >> 4, h = bh & 15;
    int q0 = blockIdx.y * 64, k0 = blockIdx.x * 64;
    int tid = threadIdx.x;
    int lr = tid >> 2;                 // 0..63
    int lc = (tid & 3) << 4;           // 0,16,32,48
    const float* qbase = q  + ((size_t)(b*512 + q0 + lr)) * 1024 + h*64 + lc;
    const float* kbase = kb + ((size_t)(b*512 + k0 + lr)) * 1024 + h*64 + lc;
    #pragma unroll
    for (int j4 = 0; j4 < 4; j4++) {
        float4 t = *(const float4*)(qbase + j4*4);
        Qs[lc + j4*4 + 0][lr] = t.x; Qs[lc + j4*4 + 1][lr] = t.y;
        Qs[lc + j4*4 + 2][lr] = t.z; Qs[lc + j4*4 + 3][lr] = t.w;
        float4 u = *(const float4*)(kbase + j4*4);
        Ks[lc + j4*4 + 0][lr] = u.x; Ks[lc + j4*4 + 1][lr] = u.y;
        Ks[lc + j4*4 + 2][lr] = u.z; Ks[lc + j4*4 + 3][lr] = u.w;
    }
    __syncthreads();
    int ty = tid >> 4, tx = tid & 15;
    float acc[4][4];
    #pragma unroll
    for (int i = 0; i < 4; i++)
        #pragma unroll
        for (int j = 0; j < 4; j++) acc[i][j] = 0.f;
    #pragma unroll
    for (int d = 0; d < 64; d++) {
        float4 a4 = *(const float4*)&Qs[d][ty*4];
        float4 b4 = *(const float4*)&Ks[d][tx*4];
        float a[4] = {a4.x,a4.y,a4.z,a4.w};
        float b[4] = {b4.x,b4.y,b4.z,b4.w};
        #pragma unroll
        for (int i = 0; i < 4; i++)
            #pragma unroll
            for (int j = 0; j < 4; j++) acc[i][j] += a[i] * b[j];
    }
    #pragma unroll
    for (int i = 0; i < 4; i++) {
        float* op = att + ((size_t)bh * 512 + q0 + ty*4 + i) * 512 + k0 + tx*4;
        *(float4*)op = make_float4(acc[i][0], acc[i][1], acc[i][2], acc[i][3]);
    }
}

__global__ void attn_softmax(float* __restrict__ att) {
    int row  = blockIdx.x * 8 + (threadIdx.x >> 5);   // < B*H*L
    int lane = threadIdx.x & 31;
    float* x = att + (size_t)row * 512;
    float v[16];
    float m = -1e30f;
    #pragma unroll
    for (int i = 0; i < 16; i++) { v[i] = x[lane + 32*i]; m = fmaxf(m, v[i]); }
    #pragma unroll
    for (int o = 16; o; o >>= 1) m = fmaxf(m, __shfl_xor_sync(0xffffffffu, m, o));
    float s = 0.f;
    #pragma unroll
    for (int i = 0; i < 16; i++) { v[i] = expf(v[i] - m); s += v[i]; }
    #pragma unroll
    for (int o = 16; o; o >>= 1) s += __shfl_xor_sync(0xffffffffu, s, o);
    float inv = 1.f / s;
    #pragma unroll
    for (int i = 0; i < 16; i++) x[lane + 32*i] = v[i] * inv;
}

// ctx[b,q,h,d] = sum_k w[b,h,q,k] * v[b,k,h,d]
__global__ __launch_bounds__(256) void attn_ctx(
    const float* __restrict__ att, const float* __restrict__ v, float* __restrict__ ctx)
{
    __shared__ float Ws[64][64];
    __shared__ float Vs[64][64];
    int bh = blockIdx.y;
    int b = bh >> 4, h = bh & 15;
    int q0 = blockIdx.x * 64;
    int tid = threadIdx.x;
    int lr = tid >> 2;
    int lc = (tid & 3) << 4;
    int ty = tid >> 4, tx = tid & 15;
    float acc[4][4];
    #pragma unroll
    for (int i = 0; i < 4; i++)
        #pragma unroll
        for (int j = 0; j < 4; j++) acc[i][j] = 0.f;

    for (int kk0 = 0; kk0 < 512; kk0 += 64) {
        const float* wbase = att + ((size_t)bh * 512 + q0 + lr) * 512 + kk0 + lc;
        #pragma unroll
        for (int j4 = 0; j4 < 4; j4++) {
            float4 t = *(const float4*)(wbase + j4*4);
            Ws[lc + j4*4 + 0][lr] = t.x; Ws[lc + j4*4 + 1][lr] = t.y;
            Ws[lc + j4*4 + 2][lr] = t.z; Ws[lc + j4*4 + 3][lr] = t.w;
        }
        const float* vbase = v + ((size_t)(b*512 + kk0 + lr)) * 1024 + h*64 + lc;
        #pragma unroll
        for (int j4 = 0; j4 < 4; j4++)
            *(float4*)&Vs[lr][lc + j4*4] = *(const float4*)(vbase + j4*4);
        __syncthreads();
        #pragma unroll
        for (int k = 0; k < 64; k++) {
            float4 a4 = *(const float4*)&Ws[k][ty*4];
            float4 b4 = *(const float4*)&Vs[k][tx*4];
            float a[4] = {a4.x,a4.y,a4.z,a4.w};
            float bb[4] = {b4.x,b4.y,b4.z,b4.w};
            #pragma unroll
            for (int i = 0; i < 4; i++)
                #pragma unroll
                for (int j = 0; j < 4; j++) acc[i][j] += a[i] * bb[j];
        }
        __syncthreads();
    }
    #pragma unroll
    for (int i = 0; i < 4; i++) {
        float* op = ctx + ((size_t)(b*512 + q0 + ty*4 + i)) * 1024 + h*64 + tx*4;
        *(float4*)op = make_float4(acc[i][0], acc[i][1], acc[i][2], acc[i][3]);
    }
}

// ---------------- head: mean over L, @ W_out + b_out, softmax ----------------
__global__ __launch_bounds__(256) void head_out(
    const float* __restrict__ W_out, const float* __restrict__ b_out, float* __restrict__ out)
{
    __shared__ float sh[4][256];
    int b = blockIdx.x;
    int tid = threadIdx.x;
    float sum[4] = {0.f, 0.f, 0.f, 0.f};
    for (int l = 0; l < 512; l++) {
        const float* p = g_prev + ((size_t)(b*512 + l)) * 1024;
        #pragma unroll
        for (int j = 0; j < 4; j++) sum[j] += p[tid + 256*j];
    }
    float part[4] = {0.f, 0.f, 0.f, 0.f};
    #pragma unroll
    for (int j = 0; j < 4; j++) {
        int d = tid + 256*j;
        float m = sum[j] * (1.f / 512.f);
        #pragma unroll
        for (int o = 0; o < 4; o++) part[o] += m * W_out[d*4 + o];
    }
    #pragma unroll
    for (int o = 0; o < 4; o++) sh[o][tid] = part[o];
    __syncthreads();
    for (int s = 128; s > 0; s >>= 1) {
        if (tid < s)
            #pragma unroll
            for (int o = 0; o < 4; o++) sh[o][tid] += sh[o][tid + s];
        __syncthreads();
    }
    if (tid == 0) {
        float a[4];
        #pragma unroll
        for (int o = 0; o < 4; o++) { a[o] = sh[o][0] + b_out[o]; out[b*4 + o] = a[o]; }
        float mx = fmaxf(fmaxf(a[0], a[1]), fmaxf(a[2], a[3]));
        float e[4], s = 0.f;
        #pragma unroll
        for (int o = 0; o < 4; o++) { e[o] = expf(a[o] - mx); s += e[o]; }
        #pragma unroll
        for (int o = 0; o < 4; o++) out[32 + b*4 + o] = e[o] / s;
    }
}

__global__ void tail_out(float* __restrict__ out) {
    int i = blockIdx.x * 256 + threadIdx.x;   // < ROWS_
    out[64 + i]        = g_rem[i];
    out[64 + 4096 + i] = g_nup[i];
}

// ---------------- launcher ----------------------------------------------------
extern "C" void kernel_launch(void* const* d_in, const int* in_sizes, int n_in,
                              void* d_out, int out_size) {
    const int*   X     = (const int*)  d_in[0];
    const float* emb   = (const float*)d_in[1];
    const float* p_w   = (const float*)d_in[2];
    const float* p_b   = (const float*)d_in[3];
    const float* Wq    = (const float*)d_in[4];
    const float* Wk    = (const float*)d_in[5];
    const float* Wv    = (const float*)d_in[6];
    const float* Wo    = (const float*)d_in[7];
    const float* ln1_g = (const float*)d_in[8];
    const float* ln1_b = (const float*)d_in[9];
    const float* ln2_g = (const float*)d_in[10];
    const float* ln2_b = (const float*)d_in[11];
    const float* K1    = (const float*)d_in[12];
    const float* c1_b  = (const float*)d_in[13];
    const float* K2    = (const float*)d_in[14];
    const float* c2_b  = (const float*)d_in[15];
    const float* W_out = (const float*)d_in[16];
    const float* b_out = (const float*)d_in[17];
    float* out = (float*)d_out;

    float *state, *xn, *q, *kb, *v, *ctx, *att, *hb;
    cudaGetSymbolAddress((void**)&state, g_state);
    cudaGetSymbolAddress((void**)&xn,    g_xn);
    cudaGetSymbolAddress((void**)&q,     g_q);
    cudaGetSymbolAddress((void**)&kb,    g_kb);
    cudaGetSymbolAddress((void**)&v,     g_v);
    cudaGetSymbolAddress((void**)&ctx,   g_ctx);
    cudaGetSymbolAddress((void**)&att,   g_att);
    cudaGetSymbolAddress((void**)&hb,    g_h);

    embed_init<<<NST_/256, 256>>>(X, emb);
    zero_act<<<16, 256>>>();

    for (int t = 0; t < NL_; t++) {
        add_time_pos<<<NST_/256, 256>>>(t);
        act_halt<<<ROWS_/8, 256>>>(p_w, p_b);
        layernorm_k<<<ROWS_, 256>>>(state, xn, ln1_g, ln1_b);

        dim3 gp(D_/128, ROWS_/128);                       // (8, 32)
        sgemm128<0><<<gp, 256>>>(xn, Wq, q,  nullptr, 0.125f, ROWS_, D_, D_);
        sgemm128<0><<<gp, 256>>>(xn, Wk, kb, nullptr, 1.f,    ROWS_, D_, D_);
        sgemm128<0><<<gp, 256>>>(xn, Wv, v,  nullptr, 1.f,    ROWS_, D_, D_);

        attn_logits<<<dim3(8, 8, B_*H_), 256>>>(q, kb, att);
        attn_softmax<<<(B_*H_*L_)/8, 256>>>(att);
        attn_ctx<<<dim3(8, B_*H_), 256>>>(att, v, ctx);

        sgemm128<1><<<gp, 256>>>(ctx, Wo, state, state, 1.f, ROWS_, D_, D_);
        layernorm_k<<<ROWS_, 256>>>(state, xn, ln2_g, ln2_b);

        convgemm128<10, 0><<<dim3(F_/128, ROWS_/128), 256>>>(xn, K1, hb, nullptr, c1_b, F_, 3*D_);
        convgemm128<12, 1><<<dim3(D_/128, ROWS_/128), 256>>>(hb, K2, state, state, c2_b, D_, 3*F_);

        prev_update<<<NST_/256, 256>>>();
    }

    head_out<<<B_, 256>>>(W_out, b_out, out);
    tail_out<<<ROWS_/256, 256>>>(out);
}

// round 5
// speedup vs baseline: 1.9852x; 1.9852x over previous
#include <cuda_runtime.h>
#include <cuda_bf16.h>
#include <cstdint>
#include <math.h>

#define B_    8
#define L_    512
#define D_    1024
#define H_    16
#define F_    4096
#define NL_   6
#define ROWS_ (B_*L_)          /* 4096 */
#define NST_  (ROWS_*D_)       /* 4194304 */

typedef __nv_bfloat16 bf16;

// ---------------- scratch (device globals; no allocation allowed) ------------
__device__ float g_state[NST_];
__device__ float g_prev [NST_];
__device__ float g_q    [NST_];
__device__ float g_kb   [NST_];
__device__ float g_v    [NST_];
__device__ float g_att  [(size_t)B_*H_*L_*L_];

__device__ bf16 g_xnh[NST_],  g_xnl[NST_];
__device__ bf16 g_ctxh[NST_], g_ctxl[NST_];
__device__ bf16 g_hh[(size_t)ROWS_*F_], g_hl[(size_t)ROWS_*F_];

// transposed+split weights [N][K]
__device__ bf16 g_Wqh[D_*D_], g_Wql[D_*D_];
__device__ bf16 g_Wkh[D_*D_], g_Wkl[D_*D_];
__device__ bf16 g_Wvh[D_*D_], g_Wvl[D_*D_];
__device__ bf16 g_Woh[D_*D_], g_Wol[D_*D_];
__device__ bf16 g_K1h[(size_t)F_*3*D_], g_K1l[(size_t)F_*3*D_];
__device__ bf16 g_K2h[(size_t)D_*3*F_], g_K2l[(size_t)D_*3*F_];

__device__ float g_hp [ROWS_];
__device__ float g_rem[ROWS_];
__device__ float g_nup[ROWS_];
__device__ float g_uw [ROWS_];

// ---------------- PTX helpers -------------------------------------------------
__device__ __forceinline__ uint32_t smem_u32(const void* p) {
    uint32_t a;
    asm("{ .reg .u64 t; cvta.to.shared.u64 t, %1; cvt.u32.u64 %0, t; }" : "=r"(a) : "l"(p));
    return a;
}
__device__ __forceinline__ void cpa16(uint32_t dst, const void* src, int sz) {
    asm volatile("cp.async.cg.shared.global [%0], [%1], 16, %2;" :: "r"(dst), "l"(src), "r"(sz));
}
__device__ __forceinline__ void ldm4(uint32_t* r, uint32_t addr) {
    asm volatile("ldmatrix.sync.aligned.m8n8.x4.shared.b16 {%0,%1,%2,%3}, [%4];"
        : "=r"(r[0]), "=r"(r[1]), "=r"(r[2]), "=r"(r[3]) : "r"(addr));
}
__device__ __forceinline__ void mma16816(float* c, const uint32_t* a, uint32_t b0, uint32_t b1) {
    asm volatile("mma.sync.aligned.m16n8k16.row.col.f32.bf16.bf16.f32 "
        "{%0,%1,%2,%3}, {%4,%5,%6,%7}, {%8,%9}, {%0,%1,%2,%3};"
        : "+f"(c[0]), "+f"(c[1]), "+f"(c[2]), "+f"(c[3])
        : "r"(a[0]), "r"(a[1]), "r"(a[2]), "r"(a[3]), "r"(b0), "r"(b1));
}

// ---------------- weight transpose + bf16 split ------------------------------
__global__ void transpose_split(const float* __restrict__ in, int inRowLen,
                                bf16* __restrict__ ohi, bf16* __restrict__ olo, int outStride)
{
    __shared__ float t[32][33];
    int n0 = blockIdx.x * 32, k0 = blockIdx.y * 32;
    int tx = threadIdx.x, ty = threadIdx.y;
    #pragma unroll
    for (int i = 0; i < 32; i += 8)
        t[ty + i][tx] = in[(size_t)(k0 + ty + i) * inRowLen + n0 + tx];
    __syncthreads();
    #pragma unroll
    for (int i = 0; i < 32; i += 8) {
        float v = t[tx][ty + i];
        bf16 h = __float2bfloat16(v);
        size_t o = (size_t)(n0 + ty + i) * outStride + k0 + tx;
        ohi[o] = h;
        olo[o] = __float2bfloat16(v - __bfloat162float(h));
    }
}

// ---------------- mma.sync GEMM ----------------------------------------------
// C[128x128] = (Ahi+Alo)@(Bhi+Blo)^T with fp32 accum (3-pass split).
// A row-major [M,K] (or implicit conv tile), B rows = output cols [N,K].
// EPI 0: Cf = acc*alpha;  EPI 1: Cf = acc+res;
// EPI 2: split(relu(acc+bias)) -> Chi/Clo;  EPI 3: Cf = acc+bias+res
#define TSTR    40                 /* halves per smem row: 32 + 8 pad */
#define TBYTES  (128*TSTR*2)       /* 10240 */
#define STAGE_B (4*TBYTES)         /* 40960 */
#define SMEM_SZ (2*STAGE_B)        /* 81920 */

__device__ __forceinline__ void ld_plain(const bf16* __restrict__ src, int row0, int K,
                                         int k0, uint32_t sbase, int tid)
{
    #pragma unroll
    for (int i = 0; i < 2; i++) {
        int unit = i * 256 + tid;
        int row = unit >> 2, ch = unit & 3;
        cpa16(sbase + row * (TSTR*2) + ch * 16,
              src + (size_t)(row0 + row) * K + k0 + ch * 8, 16);
    }
}

template<int DSHIFT>
__device__ __forceinline__ void ld_conv(const bf16* __restrict__ src, int bm,
                                        int k0, uint32_t sbase, int tid)
{
    int w  = k0 >> DSHIFT;
    int cb = k0 & ((1 << DSHIFT) - 1);
    #pragma unroll
    for (int i = 0; i < 2; i++) {
        int unit = i * 256 + tid;
        int row = unit >> 2, ch = unit & 3;
        int r = bm + row;
        int b = r >> 9;
        int l = (r & 511) + w - 1;
        int ok = ((unsigned)l < 512u);
        int lc = ok ? l : 0;
        cpa16(sbase + row * (TSTR*2) + ch * 16,
              src + (((size_t)(b * 512 + lc)) << DSHIFT) + cb + ch * 8, ok ? 16 : 0);
    }
}

template<int CONV, int DSHIFT, int EPI>
__global__ __launch_bounds__(256, 1)
void mm_gemm(const bf16* __restrict__ Ahi, const bf16* __restrict__ Alo,
             const bf16* __restrict__ Bhi, const bf16* __restrict__ Blo,
             float* __restrict__ Cf, bf16* __restrict__ Chi, bf16* __restrict__ Clo,
             const float* __restrict__ res, const float* __restrict__ bias,
             float alpha, int Nglob, int K)
{
    extern __shared__ char smem[];
    uint32_t sb = smem_u32(smem);
    int tid = threadIdx.x, wid = tid >> 5, lane = tid & 31;
    int bm = blockIdx.y * 128, bn = blockIdx.x * 128;
    int wm = wid & 3, wn = wid >> 2;        // warps 4 (m) x 2 (n)

    float acc[2][8][4];
    #pragma unroll
    for (int mt = 0; mt < 2; mt++)
        #pragma unroll
        for (int nt = 0; nt < 8; nt++)
            #pragma unroll
            for (int j = 0; j < 4; j++) acc[mt][nt][j] = 0.f;

    int nch = K >> 5;

    // prefetch stage 0
    {
        uint32_t s = sb;
        if (CONV) { ld_conv<DSHIFT>(Ahi, bm, 0, s, tid); ld_conv<DSHIFT>(Alo, bm, 0, s + TBYTES, tid); }
        else      { ld_plain(Ahi, bm, K, 0, s, tid);      ld_plain(Alo, bm, K, 0, s + TBYTES, tid); }
        ld_plain(Bhi, bn, K, 0, s + 2*TBYTES, tid);
        ld_plain(Blo, bn, K, 0, s + 3*TBYTES, tid);
        asm volatile("cp.async.commit_group;");
    }

    for (int i = 0; i < nch; i++) {
        if (i + 1 < nch) {
            uint32_t s = sb + ((i + 1) & 1) * STAGE_B;
            int k0 = (i + 1) << 5;
            if (CONV) { ld_conv<DSHIFT>(Ahi, bm, k0, s, tid); ld_conv<DSHIFT>(Alo, bm, k0, s + TBYTES, tid); }
            else      { ld_plain(Ahi, bm, K, k0, s, tid);      ld_plain(Alo, bm, K, k0, s + TBYTES, tid); }
            ld_plain(Bhi, bn, K, k0, s + 2*TBYTES, tid);
            ld_plain(Blo, bn, K, k0, s + 3*TBYTES, tid);
            asm volatile("cp.async.commit_group;");
            asm volatile("cp.async.wait_group 1;");
        } else {
            asm volatile("cp.async.wait_group 0;");
        }
        __syncthreads();

        uint32_t s = sb + (i & 1) * STAGE_B;
        #pragma unroll
        for (int ks = 0; ks < 2; ks++) {
            uint32_t ah[2][4], al[2][4];
            #pragma unroll
            for (int mt = 0; mt < 2; mt++) {
                uint32_t ra = s + (uint32_t)((wm*32 + mt*16) + (lane & 15)) * (TSTR*2)
                            + ks * 32 + (lane >> 4) * 16;
                ldm4(ah[mt], ra);
                ldm4(al[mt], ra + TBYTES);
            }
            uint32_t bh[4][4], bl[4][4];
            #pragma unroll
            for (int g = 0; g < 4; g++) {
                uint32_t rb = s + 2*TBYTES + (uint32_t)((wn*64 + g*16) + (lane & 15)) * (TSTR*2)
                            + ks * 32 + (lane >> 4) * 16;
                ldm4(bh[g], rb);
                ldm4(bl[g], rb + TBYTES);
            }
            #pragma unroll
            for (int mt = 0; mt < 2; mt++)
                #pragma unroll
                for (int nt = 0; nt < 8; nt++) {
                    int g = nt >> 1, o = nt & 1;
                    mma16816(acc[mt][nt], ah[mt], bh[g][o], bh[g][o + 2]);
                    mma16816(acc[mt][nt], ah[mt], bl[g][o], bl[g][o + 2]);
                    mma16816(acc[mt][nt], al[mt], bh[g][o], bh[g][o + 2]);
                }
        }
        __syncthreads();
    }

    // epilogue: acc mapping m16n8: c0,c1 -> row=lane>>2, cols (lane&3)*2, +1; c2,c3 -> row+8
    #pragma unroll
    for (int mt = 0; mt < 2; mt++)
        #pragma unroll
        for (int nt = 0; nt < 8; nt++)
            #pragma unroll
            for (int half = 0; half < 2; half++) {
                int row = bm + wm*32 + mt*16 + (lane >> 2) + half*8;
                int col = bn + wn*64 + nt*8 + (lane & 3)*2;
                float v0 = acc[mt][nt][half*2 + 0];
                float v1 = acc[mt][nt][half*2 + 1];
                size_t o = (size_t)row * Nglob + col;
                if (EPI == 0) {
                    *(float2*)(Cf + o) = make_float2(v0 * alpha, v1 * alpha);
                } else if (EPI == 1) {
                    float2 rr = *(const float2*)(res + o);
                    *(float2*)(Cf + o) = make_float2(v0 + rr.x, v1 + rr.y);
                } else if (EPI == 2) {
                    float2 bb = *(const float2*)(bias + col);
                    v0 = fmaxf(v0 + bb.x, 0.f);
                    v1 = fmaxf(v1 + bb.y, 0.f);
                    bf16 h0 = __float2bfloat16(v0), h1 = __float2bfloat16(v1);
                    __nv_bfloat162 hh2; hh2.x = h0; hh2.y = h1;
                    *(__nv_bfloat162*)(Chi + o) = hh2;
                    __nv_bfloat162 ll2;
                    ll2.x = __float2bfloat16(v0 - __bfloat162float(h0));
                    ll2.y = __float2bfloat16(v1 - __bfloat162float(h1));
                    *(__nv_bfloat162*)(Clo + o) = ll2;
                } else {
                    float2 rr = *(const float2*)(res + o);
                    float2 bb = *(const float2*)(bias + col);
                    *(float2*)(Cf + o) = make_float2(v0 + bb.x + rr.x, v1 + bb.y + rr.y);
                }
            }
}

// ---------------- small elementwise kernels ---------------------------------
__global__ void embed_init(const int* __restrict__ X, const float* __restrict__ emb) {
    int idx = blockIdx.x * 256 + threadIdx.x;
    int row = idx >> 10;
    int d   = idx & 1023;
    g_state[idx] = emb[(size_t)X[row] * 1024 + d];
    g_prev[idx]  = 0.f;
}

__global__ void zero_act() {
    int i = blockIdx.x * 256 + threadIdx.x;
    if (i < ROWS_) { g_hp[i] = 0.f; g_rem[i] = 0.f; g_nup[i] = 0.f; }
}

__global__ void add_time_pos(int t) {
    const float NEG_LOG_INC = -0.018024149455921103f;  // -ln(10000)/511
    int idx = blockIdx.x * 256 + threadIdx.x;
    int d = idx & 1023;
    int l = (idx >> 10) & 511;
    int i = d & 511;
    float invt = expf((float)i * NEG_LOG_INC);
    float a1 = (float)l * invt;
    float a2 = (float)t * invt;
    float v = (d < 512) ? (sinf(a1) + sinf(a2)) : (cosf(a1) + cosf(a2));
    g_state[idx] += v;
}

__global__ void act_halt(const float* __restrict__ p_w, const float* __restrict__ p_b) {
    int warp = threadIdx.x >> 5, lane = threadIdx.x & 31;
    int row  = blockIdx.x * 8 + warp;
    const float* x = g_state + (size_t)row * 1024;
    float s = 0.f;
    #pragma unroll
    for (int i = 0; i < 32; i++) s += x[lane + 32*i] * p_w[lane + 32*i];
    #pragma unroll
    for (int o = 16; o; o >>= 1) s += __shfl_xor_sync(0xffffffffu, s, o);
    if (lane == 0) {
        float p   = 1.f / (1.f + expf(-(s + p_b[0])));
        float hp  = g_hp[row], rem = g_rem[row], nup = g_nup[row];
        float still = (hp < 1.0f) ? 1.f : 0.f;
        float add   = hp + p * still;
        float nh    = ((add > 0.9f) ? 1.f : 0.f) * still;
        still       = ((add <= 0.9f) ? 1.f : 0.f) * still;
        hp  += p * still;
        rem += nh * (1.f - hp);
        hp  += nh * rem;
        nup += still + nh;
        g_hp[row] = hp; g_rem[row] = rem; g_nup[row] = nup;
        g_uw[row] = p * still + nh * rem;
    }
}

// layernorm -> bf16 hi/lo split outputs
__global__ __launch_bounds__(256) void layernorm_k(
    const float* __restrict__ in, bf16* __restrict__ ohi, bf16* __restrict__ olo,
    const float* __restrict__ g, const float* __restrict__ b)
{
    __shared__ float sh1[8], sh2[8];
    int row = blockIdx.x;
    int tid = threadIdx.x;
    const float* x = in + (size_t)row * 1024;
    float v[4];
    #pragma unroll
    for (int j = 0; j < 4; j++) v[j] = x[tid + 256*j];
    float s = v[0] + v[1] + v[2] + v[3];
    #pragma unroll
    for (int o = 16; o; o >>= 1) s += __shfl_xor_sync(0xffffffffu, s, o);
    if ((tid & 31) == 0) sh1[tid >> 5] = s;
    __syncthreads();
    float tot = 0.f;
    #pragma unroll
    for (int w = 0; w < 8; w++) tot += sh1[w];
    float mu = tot * (1.f / 1024.f);
    float q = 0.f;
    #pragma unroll
    for (int j = 0; j < 4; j++) { float d = v[j] - mu; q += d * d; }
    #pragma unroll
    for (int o = 16; o; o >>= 1) q += __shfl_xor_sync(0xffffffffu, q, o);
    if ((tid & 31) == 0) sh2[tid >> 5] = q;
    __syncthreads();
    float qt = 0.f;
    #pragma unroll
    for (int w = 0; w < 8; w++) qt += sh2[w];
    float sd  = sqrtf(qt / 1023.f);
    float inv = 1.f / (sd + 1e-6f);
    #pragma unroll
    for (int j = 0; j < 4; j++) {
        int d = tid + 256*j;
        float y = g[d] * (v[j] - mu) * inv + b[d];
        bf16 h = __float2bfloat16(y);
        size_t o = (size_t)row * 1024 + d;
        ohi[o] = h;
        olo[o] = __float2bfloat16(y - __bfloat162float(h));
    }
}

__global__ void prev_update() {
    int idx = blockIdx.x * 256 + threadIdx.x;
    int row = idx >> 10;
    float u = g_uw[row];
    g_prev[idx] = g_state[idx] * u + g_prev[idx] * (1.f - u);
}

// ---------------- attention (fp32 SIMT) ---------------------------------------
__global__ __launch_bounds__(256) void attn_logits(
    const float* __restrict__ q, const float* __restrict__ kb, float* __restrict__ att)
{
    __shared__ float Qs[64][64];
    __shared__ float Ks[64][64];
    int bh = blockIdx.z;
    int b = bh >> 4, h = bh & 15;
    int q0 = blockIdx.y * 64, k0 = blockIdx.x * 64;
    int tid = threadIdx.x;
    int lr = tid >> 2;
    int lc = (tid & 3) << 4;
    const float* qbase = q  + ((size_t)(b*512 + q0 + lr)) * 1024 + h*64 + lc;
    const float* kbase = kb + ((size_t)(b*512 + k0 + lr)) * 1024 + h*64 + lc;
    #pragma unroll
    for (int j4 = 0; j4 < 4; j4++) {
        float4 t = *(const float4*)(qbase + j4*4);
        Qs[lc + j4*4 + 0][lr] = t.x; Qs[lc + j4*4 + 1][lr] = t.y;
        Qs[lc + j4*4 + 2][lr] = t.z; Qs[lc + j4*4 + 3][lr] = t.w;
        float4 u = *(const float4*)(kbase + j4*4);
        Ks[lc + j4*4 + 0][lr] = u.x; Ks[lc + j4*4 + 1][lr] = u.y;
        Ks[lc + j4*4 + 2][lr] = u.z; Ks[lc + j4*4 + 3][lr] = u.w;
    }
    __syncthreads();
    int ty = tid >> 4, tx = tid & 15;
    float acc[4][4];
    #pragma unroll
    for (int i = 0; i < 4; i++)
        #pragma unroll
        for (int j = 0; j < 4; j++) acc[i][j] = 0.f;
    #pragma unroll
    for (int d = 0; d < 64; d++) {
        float4 a4 = *(const float4*)&Qs[d][ty*4];
        float4 b4 = *(const float4*)&Ks[d][tx*4];
        float a[4] = {a4.x,a4.y,a4.z,a4.w};
        float bb[4] = {b4.x,b4.y,b4.z,b4.w};
        #pragma unroll
        for (int i = 0; i < 4; i++)
            #pragma unroll
            for (int j = 0; j < 4; j++) acc[i][j] += a[i] * bb[j];
    }
    #pragma unroll
    for (int i = 0; i < 4; i++) {
        float* op = att + ((size_t)bh * 512 + q0 + ty*4 + i) * 512 + k0 + tx*4;
        *(float4*)op = make_float4(acc[i][0], acc[i][1], acc[i][2], acc[i][3]);
    }
}

__global__ void attn_softmax(float* __restrict__ att) {
    int row  = blockIdx.x * 8 + (threadIdx.x >> 5);
    int lane = threadIdx.x & 31;
    float* x = att + (size_t)row * 512;
    float v[16];
    float m = -1e30f;
    #pragma unroll
    for (int i = 0; i < 16; i++) { v[i] = x[lane + 32*i]; m = fmaxf(m, v[i]); }
    #pragma unroll
    for (int o = 16; o; o >>= 1) m = fmaxf(m, __shfl_xor_sync(0xffffffffu, m, o));
    float s = 0.f;
    #pragma unroll
    for (int i = 0; i < 16; i++) { v[i] = expf(v[i] - m); s += v[i]; }
    #pragma unroll
    for (int o = 16; o; o >>= 1) s += __shfl_xor_sync(0xffffffffu, s, o);
    float inv = 1.f / s;
    #pragma unroll
    for (int i = 0; i < 16; i++) x[lane + 32*i] = v[i] * inv;
}

// ctx -> bf16 hi/lo split
__global__ __launch_bounds__(256) void attn_ctx(
    const float* __restrict__ att, const float* __restrict__ v,
    bf16* __restrict__ chi, bf16* __restrict__ clo)
{
    __shared__ float Ws[64][64];
    __shared__ float Vs[64][64];
    int bh = blockIdx.y;
    int b = bh >> 4, h = bh & 15;
    int q0 = blockIdx.x * 64;
    int tid = threadIdx.x;
    int lr = tid >> 2;
    int lc = (tid & 3) << 4;
    int ty = tid >> 4, tx = tid & 15;
    float acc[4][4];
    #pragma unroll
    for (int i = 0; i < 4; i++)
        #pragma unroll
        for (int j = 0; j < 4; j++) acc[i][j] = 0.f;

    for (int kk0 = 0; kk0 < 512; kk0 += 64) {
        const float* wbase = att + ((size_t)bh * 512 + q0 + lr) * 512 + kk0 + lc;
        #pragma unroll
        for (int j4 = 0; j4 < 4; j4++) {
            float4 t = *(const float4*)(wbase + j4*4);
            Ws[lc + j4*4 + 0][lr] = t.x; Ws[lc + j4*4 + 1][lr] = t.y;
            Ws[lc + j4*4 + 2][lr] = t.z; Ws[lc + j4*4 + 3][lr] = t.w;
        }
        const float* vbase = v + ((size_t)(b*512 + kk0 + lr)) * 1024 + h*64 + lc;
        #pragma unroll
        for (int j4 = 0; j4 < 4; j4++)
            *(float4*)&Vs[lr][lc + j4*4] = *(const float4*)(vbase + j4*4);
        __syncthreads();
        #pragma unroll
        for (int k = 0; k < 64; k++) {
            float4 a4 = *(const float4*)&Ws[k][ty*4];
            float4 b4 = *(const float4*)&Vs[k][tx*4];
            float a[4] = {a4.x,a4.y,a4.z,a4.w};
            float bb[4] = {b4.x,b4.y,b4.z,b4.w};
            #pragma unroll
            for (int i = 0; i < 4; i++)
                #pragma unroll
                for (int j = 0; j < 4; j++) acc[i][j] += a[i] * bb[j];
        }
        __syncthreads();
    }
    #pragma unroll
    for (int i = 0; i < 4; i++) {
        size_t o = ((size_t)(b*512 + q0 + ty*4 + i)) * 1024 + h*64 + tx*4;
        #pragma unroll
        for (int j = 0; j < 4; j++) {
            float val = acc[i][j];
            bf16 hh = __float2bfloat16(val);
            chi[o + j] = hh;
            clo[o + j] = __float2bfloat16(val - __bfloat162float(hh));
        }
    }
}

// ---------------- head --------------------------------------------------------
__global__ __launch_bounds__(256) void head_out(
    const float* __restrict__ W_out, const float* __restrict__ b_out, float* __restrict__ out)
{
    __shared__ float sh[4][256];
    int b = blockIdx.x;
    int tid = threadIdx.x;
    float sum[4] = {0.f, 0.f, 0.f, 0.f};
    for (int l = 0; l < 512; l++) {
        const float* p = g_prev + ((size_t)(b*512 + l)) * 1024;
        #pragma unroll
        for (int j = 0; j < 4; j++) sum[j] += p[tid + 256*j];
    }
    float part[4] = {0.f, 0.f, 0.f, 0.f};
    #pragma unroll
    for (int j = 0; j < 4; j++) {
        int d = tid + 256*j;
        float m = sum[j] * (1.f / 512.f);
        #pragma unroll
        for (int o = 0; o < 4; o++) part[o] += m * W_out[d*4 + o];
    }
    #pragma unroll
    for (int o = 0; o < 4; o++) sh[o][tid] = part[o];
    __syncthreads();
    for (int s = 128; s > 0; s >>= 1) {
        if (tid < s)
            #pragma unroll
            for (int o = 0; o < 4; o++) sh[o][tid] += sh[o][tid + s];
        __syncthreads();
    }
    if (tid == 0) {
        float a[4];
        #pragma unroll
        for (int o = 0; o < 4; o++) { a[o] = sh[o][0] + b_out[o]; out[b*4 + o] = a[o]; }
        float mx = fmaxf(fmaxf(a[0], a[1]), fmaxf(a[2], a[3]));
        float e[4], s = 0.f;
        #pragma unroll
        for (int o = 0; o < 4; o++) { e[o] = expf(a[o] - mx); s += e[o]; }
        #pragma unroll
        for (int o = 0; o < 4; o++) out[32 + b*4 + o] = e[o] / s;
    }
}

__global__ void tail_out(float* __restrict__ out) {
    int i = blockIdx.x * 256 + threadIdx.x;
    out[64 + i]        = g_rem[i];
    out[64 + 4096 + i] = g_nup[i];
}

// ---------------- launcher ----------------------------------------------------
extern "C" void kernel_launch(void* const* d_in, const int* in_sizes, int n_in,
                              void* d_out, int out_size) {
    const int*   X     = (const int*)  d_in[0];
    const float* emb   = (const float*)d_in[1];
    const float* p_w   = (const float*)d_in[2];
    const float* p_b   = (const float*)d_in[3];
    const float* Wq    = (const float*)d_in[4];
    const float* Wk    = (const float*)d_in[5];
    const float* Wv    = (const float*)d_in[6];
    const float* Wo    = (const float*)d_in[7];
    const float* ln1_g = (const float*)d_in[8];
    const float* ln1_b = (const float*)d_in[9];
    const float* ln2_g = (const float*)d_in[10];
    const float* ln2_b = (const float*)d_in[11];
    const float* K1    = (const float*)d_in[12];
    const float* c1_b  = (const float*)d_in[13];
    const float* K2    = (const float*)d_in[14];
    const float* c2_b  = (const float*)d_in[15];
    const float* W_out = (const float*)d_in[16];
    const float* b_out = (const float*)d_in[17];
    float* out = (float*)d_out;

    float *state, *q, *kb, *v, *att;
    bf16 *xnh, *xnl, *ctxh, *ctxl, *hh, *hl;
    bf16 *Wqh, *Wql, *Wkh, *Wkl, *Wvh, *Wvl, *Woh, *Wol, *K1h, *K1l, *K2h, *K2l;
    cudaGetSymbolAddress((void**)&state, g_state);
    cudaGetSymbolAddress((void**)&q,     g_q);
    cudaGetSymbolAddress((void**)&kb,    g_kb);
    cudaGetSymbolAddress((void**)&v,     g_v);
    cudaGetSymbolAddress((void**)&att,   g_att);
    cudaGetSymbolAddress((void**)&xnh,   g_xnh);
    cudaGetSymbolAddress((void**)&xnl,   g_xnl);
    cudaGetSymbolAddress((void**)&ctxh,  g_ctxh);
    cudaGetSymbolAddress((void**)&ctxl,  g_ctxl);
    cudaGetSymbolAddress((void**)&hh,    g_hh);
    cudaGetSymbolAddress((void**)&hl,    g_hl);
    cudaGetSymbolAddress((void**)&Wqh,   g_Wqh);  cudaGetSymbolAddress((void**)&Wql, g_Wql);
    cudaGetSymbolAddress((void**)&Wkh,   g_Wkh);  cudaGetSymbolAddress((void**)&Wkl, g_Wkl);
    cudaGetSymbolAddress((void**)&Wvh,   g_Wvh);  cudaGetSymbolAddress((void**)&Wvl, g_Wvl);
    cudaGetSymbolAddress((void**)&Woh,   g_Woh);  cudaGetSymbolAddress((void**)&Wol, g_Wol);
    cudaGetSymbolAddress((void**)&K1h,   g_K1h);  cudaGetSymbolAddress((void**)&K1l, g_K1l);
    cudaGetSymbolAddress((void**)&K2h,   g_K2h);  cudaGetSymbolAddress((void**)&K2l, g_K2l);

    cudaFuncSetAttribute(mm_gemm<0,0,0>,  cudaFuncAttributeMaxDynamicSharedMemorySize, SMEM_SZ);
    cudaFuncSetAttribute(mm_gemm<0,0,1>,  cudaFuncAttributeMaxDynamicSharedMemorySize, SMEM_SZ);
    cudaFuncSetAttribute(mm_gemm<1,10,2>, cudaFuncAttributeMaxDynamicSharedMemorySize, SMEM_SZ);
    cudaFuncSetAttribute(mm_gemm<1,12,3>, cudaFuncAttributeMaxDynamicSharedMemorySize, SMEM_SZ);

    dim3 tb(32, 8);
    transpose_split<<<dim3(32, 32), tb>>>(Wq, 1024, Wqh, Wql, 1024);
    transpose_split<<<dim3(32, 32), tb>>>(Wk, 1024, Wkh, Wkl, 1024);
    transpose_split<<<dim3(32, 32), tb>>>(Wv, 1024, Wvh, Wvl, 1024);
    transpose_split<<<dim3(32, 32), tb>>>(Wo, 1024, Woh, Wol, 1024);
    for (int w = 0; w < 3; w++) {
        transpose_split<<<dim3(128, 32), tb>>>(K1 + (size_t)w*D_*F_, F_, K1h + w*D_, K1l + w*D_, 3*D_);
        transpose_split<<<dim3(32, 128), tb>>>(K2 + (size_t)w*F_*D_, D_, K2h + w*F_, K2l + w*F_, 3*F_);
    }

    embed_init<<<NST_/256, 256>>>(X, emb);
    zero_act<<<16, 256>>>();

    for (int t = 0; t < NL_; t++) {
        add_time_pos<<<NST_/256, 256>>>(t);
        act_halt<<<ROWS_/8, 256>>>(p_w, p_b);
        layernorm_k<<<ROWS_, 256>>>(state, xnh, xnl, ln1_g, ln1_b);

        dim3 gp(D_/128, ROWS_/128);   // (8, 32)
        mm_gemm<0,0,0><<<gp, 256, SMEM_SZ>>>(xnh, xnl, Wqh, Wql, q,  nullptr, nullptr, nullptr, nullptr, 0.125f, D_, D_);
        mm_gemm<0,0,0><<<gp, 256, SMEM_SZ>>>(xnh, xnl, Wkh, Wkl, kb, nullptr, nullptr, nullptr, nullptr, 1.f,    D_, D_);
        mm_gemm<0,0,0><<<gp, 256, SMEM_SZ>>>(xnh, xnl, Wvh, Wvl, v,  nullptr, nullptr, nullptr, nullptr, 1.f,    D_, D_);

        attn_logits<<<dim3(8, 8, B_*H_), 256>>>(q, kb, att);
        attn_softmax<<<(B_*H_*L_)/8, 256>>>(att);
        attn_ctx<<<dim3(8, B_*H_), 256>>>(att, v, ctxh, ctxl);

        mm_gemm<0,0,1><<<gp, 256, SMEM_SZ>>>(ctxh, ctxl, Woh, Wol, state, nullptr, nullptr, state, nullptr, 1.f, D_, D_);
        layernorm_k<<<ROWS_, 256>>>(state, xnh, xnl, ln2_g, ln2_b);

        mm_gemm<1,10,2><<<dim3(F_/128, ROWS_/128), 256, SMEM_SZ>>>(xnh, xnl, K1h, K1l, nullptr, hh, hl, nullptr, c1_b, 1.f, F_, 3*D_);
        mm_gemm<1,12,3><<<dim3(D_/128, ROWS_/128), 256, SMEM_SZ>>>(hh, hl, K2h, K2l, state, nullptr, nullptr, state, c2_b, 1.f, D_, 3*F_);

        prev_update<<<NST_/256, 256>>>();
    }

    head_out<<<B_, 256>>>(W_out, b_out, out);
    tail_out<<<ROWS_/256, 256>>>(out);
}

// round 6
// speedup vs baseline: 2.3714x; 1.1945x over previous
#include <cuda_runtime.h>
#include <cuda_bf16.h>
#include <cstdint>
#include <math.h>

#define B_    8
#define L_    512
#define D_    1024
#define H_    16
#define F_    4096
#define NL_   6
#define ROWS_ (B_*L_)          /* 4096 */
#define NST_  (ROWS_*D_)       /* 4194304 */

typedef __nv_bfloat16 bf16;

// ---------------- scratch (device globals; no allocation allowed) ------------
__device__ float g_state[NST_];
__device__ float g_prev [NST_];
__device__ float g_att  [(size_t)B_*H_*L_*L_];

__device__ bf16 g_xnh[NST_],  g_xnl[NST_];
__device__ bf16 g_qh[NST_],   g_ql[NST_];
__device__ bf16 g_kh[NST_],   g_kl[NST_];
__device__ bf16 g_vh[NST_],   g_vl[NST_];
__device__ bf16 g_vth[NST_],  g_vtl[NST_];
__device__ bf16 g_ctxh[NST_], g_ctxl[NST_];
__device__ bf16 g_wh[(size_t)B_*H_*L_*L_], g_wl[(size_t)B_*H_*L_*L_];
__device__ bf16 g_hh[(size_t)ROWS_*F_], g_hl[(size_t)ROWS_*F_];

// transposed+split weights [N][K]
__device__ bf16 g_Wqh[D_*D_], g_Wql[D_*D_];
__device__ bf16 g_Wkh[D_*D_], g_Wkl[D_*D_];
__device__ bf16 g_Wvh[D_*D_], g_Wvl[D_*D_];
__device__ bf16 g_Woh[D_*D_], g_Wol[D_*D_];
__device__ bf16 g_K1h[(size_t)F_*3*D_], g_K1l[(size_t)F_*3*D_];
__device__ bf16 g_K2h[(size_t)D_*3*F_], g_K2l[(size_t)D_*3*F_];

__device__ float g_hp [ROWS_];
__device__ float g_rem[ROWS_];
__device__ float g_nup[ROWS_];
__device__ float g_uw [ROWS_];

// ---------------- PTX helpers -------------------------------------------------
__device__ __forceinline__ uint32_t smem_u32(const void* p) {
    uint32_t a;
    asm("{ .reg .u64 t; cvta.to.shared.u64 t, %1; cvt.u32.u64 %0, t; }" : "=r"(a) : "l"(p));
    return a;
}
__device__ __forceinline__ void cpa16(uint32_t dst, const void* src, int sz) {
    asm volatile("cp.async.cg.shared.global [%0], [%1], 16, %2;" :: "r"(dst), "l"(src), "r"(sz));
}
__device__ __forceinline__ void ldm4(uint32_t* r, uint32_t addr) {
    asm volatile("ldmatrix.sync.aligned.m8n8.x4.shared.b16 {%0,%1,%2,%3}, [%4];"
        : "=r"(r[0]), "=r"(r[1]), "=r"(r[2]), "=r"(r[3]) : "r"(addr));
}
__device__ __forceinline__ void mma16816(float* c, const uint32_t* a, uint32_t b0, uint32_t b1) {
    asm volatile("mma.sync.aligned.m16n8k16.row.col.f32.bf16.bf16.f32 "
        "{%0,%1,%2,%3}, {%4,%5,%6,%7}, {%8,%9}, {%0,%1,%2,%3};"
        : "+f"(c[0]), "+f"(c[1]), "+f"(c[2]), "+f"(c[3])
        : "r"(a[0]), "r"(a[1]), "r"(a[2]), "r"(a[3]), "r"(b0), "r"(b1));
}
__device__ __forceinline__ void split2(float v0, float v1, bf16* hi, bf16* lo, size_t o) {
    bf16 h0 = __float2bfloat16(v0), h1 = __float2bfloat16(v1);
    __nv_bfloat162 hh2; hh2.x = h0; hh2.y = h1;
    *(__nv_bfloat162*)(hi + o) = hh2;
    __nv_bfloat162 ll2;
    ll2.x = __float2bfloat16(v0 - __bfloat162float(h0));
    ll2.y = __float2bfloat16(v1 - __bfloat162float(h1));
    *(__nv_bfloat162*)(lo + o) = ll2;
}

// ---------------- weight transpose + bf16 split ------------------------------
__global__ void transpose_split(const float* __restrict__ in, int inRowLen,
                                bf16* __restrict__ ohi, bf16* __restrict__ olo, int outStride)
{
    __shared__ float t[32][33];
    int n0 = blockIdx.x * 32, k0 = blockIdx.y * 32;
    int tx = threadIdx.x, ty = threadIdx.y;
    #pragma unroll
    for (int i = 0; i < 32; i += 8)
        t[ty + i][tx] = in[(size_t)(k0 + ty + i) * inRowLen + n0 + tx];
    __syncthreads();
    #pragma unroll
    for (int i = 0; i < 32; i += 8) {
        float v = t[tx][ty + i];
        bf16 h = __float2bfloat16(v);
        size_t o = (size_t)(n0 + ty + i) * outStride + k0 + tx;
        ohi[o] = h;
        olo[o] = __float2bfloat16(v - __bfloat162float(h));
    }
}

// per-batch bf16 transpose: in[b*512 + l][1024] -> out[b*1024 + c][512]
__global__ void transpose_b(const bf16* __restrict__ in, bf16* __restrict__ out) {
    __shared__ bf16 t[32][33];
    int b = blockIdx.z;
    int c0 = blockIdx.x * 32, l0 = blockIdx.y * 32;
    int tx = threadIdx.x, ty = threadIdx.y;
    #pragma unroll
    for (int i = 0; i < 32; i += 8)
        t[ty + i][tx] = in[((size_t)(b * 512 + l0 + ty + i)) * 1024 + c0 + tx];
    __syncthreads();
    #pragma unroll
    for (int i = 0; i < 32; i += 8)
        out[((size_t)(b * 1024 + c0 + ty + i)) * 512 + l0 + tx] = t[tx][ty + i];
}

// ---------------- mma.sync GEMM (128x128 tile) -------------------------------
// EPI 0: Cf = acc*alpha;  EPI 1: Cf = acc+res;
// EPI 2: split(relu(acc+bias));  EPI 3: Cf = acc+bias+res;  EPI 4: split(acc*alpha)
#define TSTR    40
#define TBYTES  (128*TSTR*2)       /* 10240 */
#define STAGE_B (4*TBYTES)         /* 40960 */
#define SMEM_SZ (2*STAGE_B)        /* 81920 */

__device__ __forceinline__ void ld_plain(const bf16* __restrict__ src, int row0, int K,
                                         int k0, uint32_t sbase, int tid)
{
    #pragma unroll
    for (int i = 0; i < 2; i++) {
        int unit = i * 256 + tid;
        int row = unit >> 2, ch = unit & 3;
        cpa16(sbase + row * (TSTR*2) + ch * 16,
              src + (size_t)(row0 + row) * K + k0 + ch * 8, 16);
    }
}

template<int DSHIFT>
__device__ __forceinline__ void ld_conv(const bf16* __restrict__ src, int bm,
                                        int k0, uint32_t sbase, int tid)
{
    int w  = k0 >> DSHIFT;
    int cb = k0 & ((1 << DSHIFT) - 1);
    #pragma unroll
    for (int i = 0; i < 2; i++) {
        int unit = i * 256 + tid;
        int row = unit >> 2, ch = unit & 3;
        int r = bm + row;
        int b = r >> 9;
        int l = (r & 511) + w - 1;
        int ok = ((unsigned)l < 512u);
        int lc = ok ? l : 0;
        cpa16(sbase + row * (TSTR*2) + ch * 16,
              src + (((size_t)(b * 512 + lc)) << DSHIFT) + cb + ch * 8, ok ? 16 : 0);
    }
}

template<int CONV, int DSHIFT, int EPI>
__global__ __launch_bounds__(256, 2)
void mm_gemm(const bf16* __restrict__ Ahi, const bf16* __restrict__ Alo,
             const bf16* __restrict__ Bhi, const bf16* __restrict__ Blo,
             float* __restrict__ Cf, bf16* __restrict__ Chi, bf16* __restrict__ Clo,
             const float* __restrict__ res, const float* __restrict__ bias,
             float alpha, int Nglob, int K)
{
    extern __shared__ char smem[];
    uint32_t sb = smem_u32(smem);
    int tid = threadIdx.x, wid = tid >> 5, lane = tid & 31;
    int bm = blockIdx.y * 128, bn = blockIdx.x * 128;
    int wm = wid & 3, wn = wid >> 2;

    float acc[2][8][4];
    #pragma unroll
    for (int mt = 0; mt < 2; mt++)
        #pragma unroll
        for (int nt = 0; nt < 8; nt++)
            #pragma unroll
            for (int j = 0; j < 4; j++) acc[mt][nt][j] = 0.f;

    int nch = K >> 5;

    {
        uint32_t s = sb;
        if (CONV) { ld_conv<DSHIFT>(Ahi, bm, 0, s, tid); ld_conv<DSHIFT>(Alo, bm, 0, s + TBYTES, tid); }
        else      { ld_plain(Ahi, bm, K, 0, s, tid);      ld_plain(Alo, bm, K, 0, s + TBYTES, tid); }
        ld_plain(Bhi, bn, K, 0, s + 2*TBYTES, tid);
        ld_plain(Blo, bn, K, 0, s + 3*TBYTES, tid);
        asm volatile("cp.async.commit_group;");
    }

    for (int i = 0; i < nch; i++) {
        if (i + 1 < nch) {
            uint32_t s = sb + ((i + 1) & 1) * STAGE_B;
            int k0 = (i + 1) << 5;
            if (CONV) { ld_conv<DSHIFT>(Ahi, bm, k0, s, tid); ld_conv<DSHIFT>(Alo, bm, k0, s + TBYTES, tid); }
            else      { ld_plain(Ahi, bm, K, k0, s, tid);      ld_plain(Alo, bm, K, k0, s + TBYTES, tid); }
            ld_plain(Bhi, bn, K, k0, s + 2*TBYTES, tid);
            ld_plain(Blo, bn, K, k0, s + 3*TBYTES, tid);
            asm volatile("cp.async.commit_group;");
            asm volatile("cp.async.wait_group 1;");
        } else {
            asm volatile("cp.async.wait_group 0;");
        }
        __syncthreads();

        uint32_t s = sb + (i & 1) * STAGE_B;
        #pragma unroll
        for (int ks = 0; ks < 2; ks++) {
            uint32_t ah[2][4], al[2][4];
            #pragma unroll
            for (int mt = 0; mt < 2; mt++) {
                uint32_t ra = s + (uint32_t)((wm*32 + mt*16) + (lane & 15)) * (TSTR*2)
                            + ks * 32 + (lane >> 4) * 16;
                ldm4(ah[mt], ra);
                ldm4(al[mt], ra + TBYTES);
            }
            uint32_t bh[4][4], bl[4][4];
            #pragma unroll
            for (int g = 0; g < 4; g++) {
                uint32_t rb = s + 2*TBYTES + (uint32_t)((wn*64 + g*16) + (lane & 15)) * (TSTR*2)
                            + ks * 32 + (lane >> 4) * 16;
                ldm4(bh[g], rb);
                ldm4(bl[g], rb + TBYTES);
            }
            #pragma unroll
            for (int mt = 0; mt < 2; mt++)
                #pragma unroll
                for (int nt = 0; nt < 8; nt++) {
                    int g = nt >> 1, o = nt & 1;
                    mma16816(acc[mt][nt], ah[mt], bh[g][o], bh[g][o + 2]);
                    mma16816(acc[mt][nt], ah[mt], bl[g][o], bl[g][o + 2]);
                    mma16816(acc[mt][nt], al[mt], bh[g][o], bh[g][o + 2]);
                }
        }
        __syncthreads();
    }

    #pragma unroll
    for (int mt = 0; mt < 2; mt++)
        #pragma unroll
        for (int nt = 0; nt < 8; nt++)
            #pragma unroll
            for (int half = 0; half < 2; half++) {
                int row = bm + wm*32 + mt*16 + (lane >> 2) + half*8;
                int col = bn + wn*64 + nt*8 + (lane & 3)*2;
                float v0 = acc[mt][nt][half*2 + 0];
                float v1 = acc[mt][nt][half*2 + 1];
                size_t o = (size_t)row * Nglob + col;
                if (EPI == 0) {
                    *(float2*)(Cf + o) = make_float2(v0 * alpha, v1 * alpha);
                } else if (EPI == 1) {
                    float2 rr = *(const float2*)(res + o);
                    *(float2*)(Cf + o) = make_float2(v0 + rr.x, v1 + rr.y);
                } else if (EPI == 2) {
                    float2 bb = *(const float2*)(bias + col);
                    v0 = fmaxf(v0 + bb.x, 0.f);
                    v1 = fmaxf(v1 + bb.y, 0.f);
                    split2(v0, v1, Chi, Clo, o);
                } else if (EPI == 3) {
                    float2 rr = *(const float2*)(res + o);
                    float2 bb = *(const float2*)(bias + col);
                    *(float2*)(Cf + o) = make_float2(v0 + bb.x + rr.x, v1 + bb.y + rr.y);
                } else {
                    split2(v0 * alpha, v1 * alpha, Chi, Clo, o);
                }
            }
}

// ---------------- attention: logits = q@k^T (per bh), K=64 --------------------
#define QSTR 72
#define QTB  (128*QSTR*2)   /* 18432 */
#define QSMEM (4*QTB)       /* 73728 */

__global__ __launch_bounds__(256, 2)
void attn_qk(const bf16* __restrict__ qh, const bf16* __restrict__ ql,
             const bf16* __restrict__ kh, const bf16* __restrict__ kl,
             float* __restrict__ att)
{
    extern __shared__ char smem[];
    uint32_t sb = smem_u32(smem);
    int tid = threadIdx.x, wid = tid >> 5, lane = tid & 31;
    int bz = blockIdx.z;
    int b = bz >> 4, h = bz & 15;
    size_t qbase = (size_t)b*524288 + h*64 + (size_t)blockIdx.y*131072;
    size_t kbase = (size_t)b*524288 + h*64 + (size_t)blockIdx.x*131072;

    #pragma unroll
    for (int i = 0; i < 4; i++) {
        int unit = i * 256 + tid;
        int row = unit >> 3, ch = unit & 7;
        uint32_t d = (uint32_t)(row * (QSTR*2) + ch * 16);
        size_t so = (size_t)row * 1024 + ch * 8;
        cpa16(sb + d,         qh + qbase + so, 16);
        cpa16(sb + QTB + d,   ql + qbase + so, 16);
        cpa16(sb + 2*QTB + d, kh + kbase + so, 16);
        cpa16(sb + 3*QTB + d, kl + kbase + so, 16);
    }
    asm volatile("cp.async.commit_group;");
    asm volatile("cp.async.wait_group 0;");
    __syncthreads();

    int wm = wid & 3, wn = wid >> 2;
    float acc[2][8][4];
    #pragma unroll
    for (int mt = 0; mt < 2; mt++)
        #pragma unroll
        for (int nt = 0; nt < 8; nt++)
            #pragma unroll
            for (int j = 0; j < 4; j++) acc[mt][nt][j] = 0.f;

    #pragma unroll
    for (int ks = 0; ks < 4; ks++) {
        uint32_t ah[2][4], al[2][4];
        #pragma unroll
        for (int mt = 0; mt < 2; mt++) {
            uint32_t ra = sb + (uint32_t)((wm*32 + mt*16) + (lane & 15)) * (QSTR*2)
                        + ks * 32 + (lane >> 4) * 16;
            ldm4(ah[mt], ra);
            ldm4(al[mt], ra + QTB);
        }
        uint32_t bh[4][4], bl[4][4];
        #pragma unroll
        for (int g = 0; g < 4; g++) {
            uint32_t rb = sb + 2*QTB + (uint32_t)((wn*64 + g*16) + (lane & 15)) * (QSTR*2)
                        + ks * 32 + (lane >> 4) * 16;
            ldm4(bh[g], rb);
            ldm4(bl[g], rb + QTB);
        }
        #pragma unroll
        for (int mt = 0; mt < 2; mt++)
            #pragma unroll
            for (int nt = 0; nt < 8; nt++) {
                int g = nt >> 1, o = nt & 1;
                mma16816(acc[mt][nt], ah[mt], bh[g][o], bh[g][o + 2]);
                mma16816(acc[mt][nt], ah[mt], bl[g][o], bl[g][o + 2]);
                mma16816(acc[mt][nt], al[mt], bh[g][o], bh[g][o + 2]);
            }
    }

    #pragma unroll
    for (int mt = 0; mt < 2; mt++)
        #pragma unroll
        for (int nt = 0; nt < 8; nt++)
            #pragma unroll
            for (int half = 0; half < 2; half++) {
                int rloc = wm*32 + mt*16 + (lane >> 2) + half*8;
                int cloc = wn*64 + nt*8 + (lane & 3)*2;
                float* ap = att + ((size_t)bz*512 + blockIdx.y*128 + rloc)*512
                          + blockIdx.x*128 + cloc;
                *(float2*)ap = make_float2(acc[mt][nt][half*2], acc[mt][nt][half*2 + 1]);
            }
}

// ---------------- attention: ctx = w@v (per bh), tile 128x64, K=512 -----------
#define WA_B  (128*TSTR*2)   /* 10240 */
#define WB_B  (64*TSTR*2)    /* 5120 */
#define WSTAGE (2*WA_B + 2*WB_B)   /* 30720 */
#define WSMEM (2*WSTAGE)           /* 61440 */

__global__ __launch_bounds__(256, 2)
void attn_wv(const bf16* __restrict__ wh, const bf16* __restrict__ wl,
             const bf16* __restrict__ vth, const bf16* __restrict__ vtl,
             bf16* __restrict__ ctxh, bf16* __restrict__ ctxl)
{
    extern __shared__ char smem[];
    uint32_t sb = smem_u32(smem);
    int tid = threadIdx.x, wid = tid >> 5, lane = tid & 31;
    int bz = blockIdx.y;
    int b = bz >> 4, h = bz & 15;
    size_t abase = (size_t)bz*262144 + (size_t)blockIdx.x*65536;
    size_t bbase = (size_t)bz*32768;
    int wm = wid & 3, wn = wid >> 2;

    float acc[2][4][4];
    #pragma unroll
    for (int mt = 0; mt < 2; mt++)
        #pragma unroll
        for (int nt = 0; nt < 4; nt++)
            #pragma unroll
            for (int j = 0; j < 4; j++) acc[mt][nt][j] = 0.f;

    // load chunk k0 into stage s
    auto load_chunk = [&](int k0, uint32_t s) {
        #pragma unroll
        for (int i = 0; i < 2; i++) {
            int unit = i * 256 + tid;
            int row = unit >> 2, ch = unit & 3;
            uint32_t d = (uint32_t)(row * (TSTR*2) + ch * 16);
            size_t so = abase + (size_t)row * 512 + k0 + ch * 8;
            cpa16(s + d,        wh + so, 16);
            cpa16(s + WA_B + d, wl + so, 16);
        }
        {
            int row = tid >> 2, ch = tid & 3;
            uint32_t d = (uint32_t)(row * (TSTR*2) + ch * 16);
            size_t so = bbase + (size_t)row * 512 + k0 + ch * 8;
            cpa16(s + 2*WA_B + d,        vth + so, 16);
            cpa16(s + 2*WA_B + WB_B + d, vtl + so, 16);
        }
    };

    load_chunk(0, sb);
    asm volatile("cp.async.commit_group;");

    for (int i = 0; i < 16; i++) {
        if (i + 1 < 16) {
            load_chunk((i + 1) << 5, sb + ((i + 1) & 1) * WSTAGE);
            asm volatile("cp.async.commit_group;");
            asm volatile("cp.async.wait_group 1;");
        } else {
            asm volatile("cp.async.wait_group 0;");
        }
        __syncthreads();

        uint32_t s = sb + (i & 1) * WSTAGE;
        #pragma unroll
        for (int ks = 0; ks < 2; ks++) {
            uint32_t ah[2][4], al[2][4];
            #pragma unroll
            for (int mt = 0; mt < 2; mt++) {
                uint32_t ra = s + (uint32_t)((wm*32 + mt*16) + (lane & 15)) * (TSTR*2)
                            + ks * 32 + (lane >> 4) * 16;
                ldm4(ah[mt], ra);
                ldm4(al[mt], ra + WA_B);
            }
            uint32_t bh[2][4], bl[2][4];
            #pragma unroll
            for (int g = 0; g < 2; g++) {
                uint32_t rb = s + 2*WA_B + (uint32_t)((wn*32 + g*16) + (lane & 15)) * (TSTR*2)
                            + ks * 32 + (lane >> 4) * 16;
                ldm4(bh[g], rb);
                ldm4(bl[g], rb + WB_B);
            }
            #pragma unroll
            for (int mt = 0; mt < 2; mt++)
                #pragma unroll
                for (int nt = 0; nt < 4; nt++) {
                    int g = nt >> 1, o = nt & 1;
                    mma16816(acc[mt][nt], ah[mt], bh[g][o], bh[g][o + 2]);
                    mma16816(acc[mt][nt], ah[mt], bl[g][o], bl[g][o + 2]);
                    mma16816(acc[mt][nt], al[mt], bh[g][o], bh[g][o + 2]);
                }
        }
        __syncthreads();
    }

    #pragma unroll
    for (int mt = 0; mt < 2; mt++)
        #pragma unroll
        for (int nt = 0; nt < 4; nt++)
            #pragma unroll
            for (int half = 0; half < 2; half++) {
                int rloc = wm*32 + mt*16 + (lane >> 2) + half*8;
                int row = b*512 + blockIdx.x*128 + rloc;
                int col = h*64 + wn*32 + nt*8 + (lane & 3)*2;
                size_t o = (size_t)row * 1024 + col;
                split2(acc[mt][nt][half*2], acc[mt][nt][half*2 + 1], ctxh, ctxl, o);
            }
}

// ---------------- softmax + bf16 split ----------------------------------------
__global__ void softmax_split(const float* __restrict__ att,
                              bf16* __restrict__ wh, bf16* __restrict__ wl)
{
    int row  = blockIdx.x * 8 + (threadIdx.x >> 5);
    int lane = threadIdx.x & 31;
    const float* x = att + (size_t)row * 512;
    float v[16];
    float m = -1e30f;
    #pragma unroll
    for (int i = 0; i < 16; i++) { v[i] = x[lane + 32*i]; m = fmaxf(m, v[i]); }
    #pragma unroll
    for (int o = 16; o; o >>= 1) m = fmaxf(m, __shfl_xor_sync(0xffffffffu, m, o));
    float s = 0.f;
    #pragma unroll
    for (int i = 0; i < 16; i++) { v[i] = expf(v[i] - m); s += v[i]; }
    #pragma unroll
    for (int o = 16; o; o >>= 1) s += __shfl_xor_sync(0xffffffffu, s, o);
    float inv = 1.f / s;
    #pragma unroll
    for (int i = 0; i < 16; i++) {
        float w = v[i] * inv;
        bf16 hh = __float2bfloat16(w);
        size_t o = (size_t)row * 512 + lane + 32*i;
        wh[o] = hh;
        wl[o] = __float2bfloat16(w - __bfloat162float(hh));
    }
}

// ---------------- fused: time/pos add + ACT halt + layernorm1 -----------------
__global__ __launch_bounds__(256) void pre_layer(
    int t, const float* __restrict__ p_w, const float* __restrict__ p_b,
    const float* __restrict__ g, const float* __restrict__ bgm)
{
    __shared__ float sh1[8], sh2[8], sh3[8];
    const float NEG_LOG_INC = -0.018024149455921103f;
    int row = blockIdx.x;
    int l   = row & 511;
    int tid = threadIdx.x;
    float* x = g_state + (size_t)row * 1024;
    float v[4];
    float sum = 0.f, dot = 0.f;
    #pragma unroll
    for (int j = 0; j < 4; j++) {
        int d = tid + 256*j;
        int i = d & 511;
        float invt = expf((float)i * NEG_LOG_INC);
        float a1 = (float)l * invt;
        float a2 = (float)t * invt;
        float sig = (d < 512) ? (sinf(a1) + sinf(a2)) : (cosf(a1) + cosf(a2));
        float val = x[d] + sig;
        x[d] = val;
        v[j] = val;
        sum += val;
        dot += val * p_w[d];
    }
    #pragma unroll
    for (int o = 16; o; o >>= 1) {
        sum += __shfl_xor_sync(0xffffffffu, sum, o);
        dot += __shfl_xor_sync(0xffffffffu, dot, o);
    }
    if ((tid & 31) == 0) { sh1[tid >> 5] = sum; sh3[tid >> 5] = dot; }
    __syncthreads();
    float tot = 0.f, dtot = 0.f;
    #pragma unroll
    for (int w = 0; w < 8; w++) { tot += sh1[w]; dtot += sh3[w]; }
    float mu = tot * (1.f / 1024.f);
    float q = 0.f;
    #pragma unroll
    for (int j = 0; j < 4; j++) { float d = v[j] - mu; q += d * d; }
    #pragma unroll
    for (int o = 16; o; o >>= 1) q += __shfl_xor_sync(0xffffffffu, q, o);
    if ((tid & 31) == 0) sh2[tid >> 5] = q;
    __syncthreads();

    if (tid == 0) {
        float p   = 1.f / (1.f + expf(-(dtot + p_b[0])));
        float hp  = g_hp[row], rem = g_rem[row], nup = g_nup[row];
        float still = (hp < 1.0f) ? 1.f : 0.f;
        float add   = hp + p * still;
        float nh    = ((add > 0.9f) ? 1.f : 0.f) * still;
        still       = ((add <= 0.9f) ? 1.f : 0.f) * still;
        hp  += p * still;
        rem += nh * (1.f - hp);
        hp  += nh * rem;
        nup += still + nh;
        g_hp[row] = hp; g_rem[row] = rem; g_nup[row] = nup;
        g_uw[row] = p * still + nh * rem;
    }

    float qt = 0.f;
    #pragma unroll
    for (int w = 0; w < 8; w++) qt += sh2[w];
    float sd  = sqrtf(qt / 1023.f);
    float inv = 1.f / (sd + 1e-6f);
    #pragma unroll
    for (int j = 0; j < 4; j++) {
        int d = tid + 256*j;
        float y = g[d] * (v[j] - mu) * inv + bgm[d];
        bf16 h = __float2bfloat16(y);
        size_t o = (size_t)row * 1024 + d;
        g_xnh[o] = h;
        g_xnl[o] = __float2bfloat16(y - __bfloat162float(h));
    }
}

// ---------------- misc elementwise --------------------------------------------
__global__ void embed_init(const int* __restrict__ X, const float* __restrict__ emb) {
    int idx = blockIdx.x * 256 + threadIdx.x;
    int row = idx >> 10;
    int d   = idx & 1023;
    g_state[idx] = emb[(size_t)X[row] * 1024 + d];
    g_prev[idx]  = 0.f;
}

__global__ void zero_act() {
    int i = blockIdx.x * 256 + threadIdx.x;
    if (i < ROWS_) { g_hp[i] = 0.f; g_rem[i] = 0.f; g_nup[i] = 0.f; }
}

// layernorm (fp32 in) -> bf16 hi/lo split outputs  (used for ln2)
__global__ __launch_bounds__(256) void layernorm_k(
    const float* __restrict__ in, bf16* __restrict__ ohi, bf16* __restrict__ olo,
    const float* __restrict__ g, const float* __restrict__ b)
{
    __shared__ float sh1[8], sh2[8];
    int row = blockIdx.x;
    int tid = threadIdx.x;
    const float* x = in + (size_t)row * 1024;
    float v[4];
    #pragma unroll
    for (int j = 0; j < 4; j++) v[j] = x[tid + 256*j];
    float s = v[0] + v[1] + v[2] + v[3];
    #pragma unroll
    for (int o = 16; o; o >>= 1) s += __shfl_xor_sync(0xffffffffu, s, o);
    if ((tid & 31) == 0) sh1[tid >> 5] = s;
    __syncthreads();
    float tot = 0.f;
    #pragma unroll
    for (int w = 0; w < 8; w++) tot += sh1[w];
    float mu = tot * (1.f / 1024.f);
    float q = 0.f;
    #pragma unroll
    for (int j = 0; j < 4; j++) { float d = v[j] - mu; q += d * d; }
    #pragma unroll
    for (int o = 16; o; o >>= 1) q += __shfl_xor_sync(0xffffffffu, q, o);
    if ((tid & 31) == 0) sh2[tid >> 5] = q;
    __syncthreads();
    float qt = 0.f;
    #pragma unroll
    for (int w = 0; w < 8; w++) qt += sh2[w];
    float sd  = sqrtf(qt / 1023.f);
    float inv = 1.f / (sd + 1e-6f);
    #pragma unroll
    for (int j = 0; j < 4; j++) {
        int d = tid + 256*j;
        float y = g[d] * (v[j] - mu) * inv + b[d];
        bf16 h = __float2bfloat16(y);
        size_t o = (size_t)row * 1024 + d;
        ohi[o] = h;
        olo[o] = __float2bfloat16(y - __bfloat162float(h));
    }
}

__global__ void prev_update() {
    int idx = blockIdx.x * 256 + threadIdx.x;
    int row = idx >> 10;
    float u = g_uw[row];
    g_prev[idx] = g_state[idx] * u + g_prev[idx] * (1.f - u);
}

// ---------------- head --------------------------------------------------------
__global__ __launch_bounds__(256) void head_out(
    const float* __restrict__ W_out, const float* __restrict__ b_out, float* __restrict__ out)
{
    __shared__ float sh[4][256];
    int b = blockIdx.x;
    int tid = threadIdx.x;
    float sum[4] = {0.f, 0.f, 0.f, 0.f};
    for (int l = 0; l < 512; l++) {
        const float* p = g_prev + ((size_t)(b*512 + l)) * 1024;
        #pragma unroll
        for (int j = 0; j < 4; j++) sum[j] += p[tid + 256*j];
    }
    float part[4] = {0.f, 0.f, 0.f, 0.f};
    #pragma unroll
    for (int j = 0; j < 4; j++) {
        int d = tid + 256*j;
        float m = sum[j] * (1.f / 512.f);
        #pragma unroll
        for (int o = 0; o < 4; o++) part[o] += m * W_out[d*4 + o];
    }
    #pragma unroll
    for (int o = 0; o < 4; o++) sh[o][tid] = part[o];
    __syncthreads();
    for (int s = 128; s > 0; s >>= 1) {
        if (tid < s)
            #pragma unroll
            for (int o = 0; o < 4; o++) sh[o][tid] += sh[o][tid + s];
        __syncthreads();
    }
    if (tid == 0) {
        float a[4];
        #pragma unroll
        for (int o = 0; o < 4; o++) { a[o] = sh[o][0] + b_out[o]; out[b*4 + o] = a[o]; }
        float mx = fmaxf(fmaxf(a[0], a[1]), fmaxf(a[2], a[3]));
        float e[4], s = 0.f;
        #pragma unroll
        for (int o = 0; o < 4; o++) { e[o] = expf(a[o] - mx); s += e[o]; }
        #pragma unroll
        for (int o = 0; o < 4; o++) out[32 + b*4 + o] = e[o] / s;
    }
}

__global__ void tail_out(float* __restrict__ out) {
    int i = blockIdx.x * 256 + threadIdx.x;
    out[64 + i]        = g_rem[i];
    out[64 + 4096 + i] = g_nup[i];
}

// ---------------- launcher ----------------------------------------------------
extern "C" void kernel_launch(void* const* d_in, const int* in_sizes, int n_in,
                              void* d_out, int out_size) {
    const int*   X     = (const int*)  d_in[0];
    const float* emb   = (const float*)d_in[1];
    const float* p_w   = (const float*)d_in[2];
    const float* p_b   = (const float*)d_in[3];
    const float* Wq    = (const float*)d_in[4];
    const float* Wk    = (const float*)d_in[5];
    const float* Wv    = (const float*)d_in[6];
    const float* Wo    = (const float*)d_in[7];
    const float* ln1_g = (const float*)d_in[8];
    const float* ln1_b = (const float*)d_in[9];
    const float* ln2_g = (const float*)d_in[10];
    const float* ln2_b = (const float*)d_in[11];
    const float* K1    = (const float*)d_in[12];
    const float* c1_b  = (const float*)d_in[13];
    const float* K2    = (const float*)d_in[14];
    const float* c2_b  = (const float*)d_in[15];
    const float* W_out = (const float*)d_in[16];
    const float* b_out = (const float*)d_in[17];
    float* out = (float*)d_out;

    float *state, *att;
    bf16 *xnh, *xnl, *qh, *ql, *kh, *kl, *vh, *vl, *vth, *vtl, *ctxh, *ctxl, *wh, *wl, *hh, *hl;
    bf16 *Wqh, *Wql, *Wkh, *Wkl, *Wvh, *Wvl, *Woh, *Wol, *K1h, *K1l, *K2h, *K2l;
    cudaGetSymbolAddress((void**)&state, g_state);
    cudaGetSymbolAddress((void**)&att,   g_att);
    cudaGetSymbolAddress((void**)&xnh,   g_xnh);   cudaGetSymbolAddress((void**)&xnl, g_xnl);
    cudaGetSymbolAddress((void**)&qh,    g_qh);    cudaGetSymbolAddress((void**)&ql,  g_ql);
    cudaGetSymbolAddress((void**)&kh,    g_kh);    cudaGetSymbolAddress((void**)&kl,  g_kl);
    cudaGetSymbolAddress((void**)&vh,    g_vh);    cudaGetSymbolAddress((void**)&vl,  g_vl);
    cudaGetSymbolAddress((void**)&vth,   g_vth);   cudaGetSymbolAddress((void**)&vtl, g_vtl);
    cudaGetSymbolAddress((void**)&ctxh,  g_ctxh);  cudaGetSymbolAddress((void**)&ctxl,g_ctxl);
    cudaGetSymbolAddress((void**)&wh,    g_wh);    cudaGetSymbolAddress((void**)&wl,  g_wl);
    cudaGetSymbolAddress((void**)&hh,    g_hh);    cudaGetSymbolAddress((void**)&hl,  g_hl);
    cudaGetSymbolAddress((void**)&Wqh,   g_Wqh);   cudaGetSymbolAddress((void**)&Wql, g_Wql);
    cudaGetSymbolAddress((void**)&Wkh,   g_Wkh);   cudaGetSymbolAddress((void**)&Wkl, g_Wkl);
    cudaGetSymbolAddress((void**)&Wvh,   g_Wvh);   cudaGetSymbolAddress((void**)&Wvl, g_Wvl);
    cudaGetSymbolAddress((void**)&Woh,   g_Woh);   cudaGetSymbolAddress((void**)&Wol, g_Wol);
    cudaGetSymbolAddress((void**)&K1h,   g_K1h);   cudaGetSymbolAddress((void**)&K1l, g_K1l);
    cudaGetSymbolAddress((void**)&K2h,   g_K2h);   cudaGetSymbolAddress((void**)&K2l, g_K2l);

    cudaFuncSetAttribute(mm_gemm<0,0,1>,  cudaFuncAttributeMaxDynamicSharedMemorySize, SMEM_SZ);
    cudaFuncSetAttribute(mm_gemm<0,0,4>,  cudaFuncAttributeMaxDynamicSharedMemorySize, SMEM_SZ);
    cudaFuncSetAttribute(mm_gemm<1,10,2>, cudaFuncAttributeMaxDynamicSharedMemorySize, SMEM_SZ);
    cudaFuncSetAttribute(mm_gemm<1,12,3>, cudaFuncAttributeMaxDynamicSharedMemorySize, SMEM_SZ);
    cudaFuncSetAttribute(attn_qk, cudaFuncAttributeMaxDynamicSharedMemorySize, QSMEM);
    cudaFuncSetAttribute(attn_wv, cudaFuncAttributeMaxDynamicSharedMemorySize, WSMEM);

    dim3 tb(32, 8);
    transpose_split<<<dim3(32, 32), tb>>>(Wq, 1024, Wqh, Wql, 1024);
    transpose_split<<<dim3(32, 32), tb>>>(Wk, 1024, Wkh, Wkl, 1024);
    transpose_split<<<dim3(32, 32), tb>>>(Wv, 1024, Wvh, Wvl, 1024);
    transpose_split<<<dim3(32, 32), tb>>>(Wo, 1024, Woh, Wol, 1024);
    for (int w = 0; w < 3; w++) {
        transpose_split<<<dim3(128, 32), tb>>>(K1 + (size_t)w*D_*F_, F_, K1h + w*D_, K1l + w*D_, 3*D_);
        transpose_split<<<dim3(32, 128), tb>>>(K2 + (size_t)w*F_*D_, D_, K2h + w*F_, K2l + w*F_, 3*F_);
    }

    embed_init<<<NST_/256, 256>>>(X, emb);
    zero_act<<<16, 256>>>();

    for (int t = 0; t < NL_; t++) {
        pre_layer<<<ROWS_, 256>>>(t, p_w, p_b, ln1_g, ln1_b);

        dim3 gp(D_/128, ROWS_/128);   // (8, 32)
        mm_gemm<0,0,4><<<gp, 256, SMEM_SZ>>>(xnh, xnl, Wqh, Wql, nullptr, qh, ql, nullptr, nullptr, 0.125f, D_, D_);
        mm_gemm<0,0,4><<<gp, 256, SMEM_SZ>>>(xnh, xnl, Wkh, Wkl, nullptr, kh, kl, nullptr, nullptr, 1.f,    D_, D_);
        mm_gemm<0,0,4><<<gp, 256, SMEM_SZ>>>(xnh, xnl, Wvh, Wvl, nullptr, vh, vl, nullptr, nullptr, 1.f,    D_, D_);

        transpose_b<<<dim3(32, 16, 8), tb>>>(vh, vth);
        transpose_b<<<dim3(32, 16, 8), tb>>>(vl, vtl);

        attn_qk<<<dim3(4, 4, B_*H_), 256, QSMEM>>>(qh, ql, kh, kl, att);
        softmax_split<<<(B_*H_*L_)/8, 256>>>(att, wh, wl);
        attn_wv<<<dim3(4, B_*H_), 256, WSMEM>>>(wh, wl, vth, vtl, ctxh, ctxl);

        mm_gemm<0,0,1><<<gp, 256, SMEM_SZ>>>(ctxh, ctxl, Woh, Wol, state, nullptr, nullptr, state, nullptr, 1.f, D_, D_);
        layernorm_k<<<ROWS_, 256>>>(state, xnh, xnl, ln2_g, ln2_b);

        mm_gemm<1,10,2><<<dim3(F_/128, ROWS_/128), 256, SMEM_SZ>>>(xnh, xnl, K1h, K1l, nullptr, hh, hl, nullptr, c1_b, 1.f, F_, 3*D_);
        mm_gemm<1,12,3><<<dim3(D_/128, ROWS_/128), 256, SMEM_SZ>>>(hh, hl, K2h, K2l, state, nullptr, nullptr, state, c2_b, 1.f, D_, 3*F_);

        prev_update<<<NST_/256, 256>>>();
    }

    head_out<<<B_, 256>>>(W_out, b_out, out);
    tail_out<<<ROWS_/256, 256>>>(out);
}

// round 11
// speedup vs baseline: 2.3872x; 1.0067x over previous
#include <cuda_runtime.h>
#include <cuda_bf16.h>
#include <cstdint>
#include <math.h>

#define B_    8
#define L_    512
#define D_    1024
#define H_    16
#define F_    4096
#define NL_   6
#define ROWS_ (B_*L_)          /* 4096 */
#define NST_  (ROWS_*D_)       /* 4194304 */

typedef __nv_bfloat16 bf16;

// ---------------- scratch (device globals; no allocation allowed) ------------
__device__ float g_state[NST_];
__device__ float g_prev [NST_];
__device__ float g_att  [(size_t)B_*H_*L_*L_];

__device__ bf16 g_xnh[NST_],  g_xnl[NST_];
__device__ bf16 g_qkvh[(size_t)ROWS_*3*D_], g_qkvl[(size_t)ROWS_*3*D_];
__device__ bf16 g_vth[NST_],  g_vtl[NST_];
__device__ bf16 g_ctxh[NST_], g_ctxl[NST_];
__device__ bf16 g_wh[(size_t)B_*H_*L_*L_], g_wl[(size_t)B_*H_*L_*L_];
__device__ bf16 g_hh[(size_t)ROWS_*F_], g_hl[(size_t)ROWS_*F_];

// transposed+split weights [N][K]
__device__ bf16 g_Wqkvh[3*D_*D_], g_Wqkvl[3*D_*D_];
__device__ bf16 g_Woh[D_*D_], g_Wol[D_*D_];
__device__ bf16 g_K1h[(size_t)F_*3*D_], g_K1l[(size_t)F_*3*D_];
__device__ bf16 g_K2h[(size_t)D_*3*F_], g_K2l[(size_t)D_*3*F_];

__device__ float g_hp [ROWS_];
__device__ float g_rem[ROWS_];
__device__ float g_nup[ROWS_];
__device__ float g_uw [ROWS_];

// ---------------- PTX helpers -------------------------------------------------
__device__ __forceinline__ uint32_t smem_u32(const void* p) {
    uint32_t a;
    asm("{ .reg .u64 t; cvta.to.shared.u64 t, %1; cvt.u32.u64 %0, t; }" : "=r"(a) : "l"(p));
    return a;
}
__device__ __forceinline__ void cpa16(uint32_t dst, const void* src, int sz) {
    asm volatile("cp.async.cg.shared.global [%0], [%1], 16, %2;" :: "r"(dst), "l"(src), "r"(sz));
}
__device__ __forceinline__ void ldm4(uint32_t* r, uint32_t addr) {
    asm volatile("ldmatrix.sync.aligned.m8n8.x4.shared.b16 {%0,%1,%2,%3}, [%4];"
        : "=r"(r[0]), "=r"(r[1]), "=r"(r[2]), "=r"(r[3]) : "r"(addr));
}
__device__ __forceinline__ void mma16816(float* c, const uint32_t* a, uint32_t b0, uint32_t b1) {
    asm volatile("mma.sync.aligned.m16n8k16.row.col.f32.bf16.bf16.f32 "
        "{%0,%1,%2,%3}, {%4,%5,%6,%7}, {%8,%9}, {%0,%1,%2,%3};"
        : "+f"(c[0]), "+f"(c[1]), "+f"(c[2]), "+f"(c[3])
        : "r"(a[0]), "r"(a[1]), "r"(a[2]), "r"(a[3]), "r"(b0), "r"(b1));
}
__device__ __forceinline__ void split2(float v0, float v1, bf16* hi, bf16* lo, size_t o) {
    bf16 h0 = __float2bfloat16(v0), h1 = __float2bfloat16(v1);
    __nv_bfloat162 hh2; hh2.x = h0; hh2.y = h1;
    *(__nv_bfloat162*)(hi + o) = hh2;
    __nv_bfloat162 ll2;
    ll2.x = __float2bfloat16(v0 - __bfloat162float(h0));
    ll2.y = __float2bfloat16(v1 - __bfloat162float(h1));
    *(__nv_bfloat162*)(lo + o) = ll2;
}

// ---------------- weight transpose + bf16 split ------------------------------
__global__ void transpose_split(const float* __restrict__ in, int inRowLen,
                                bf16* __restrict__ ohi, bf16* __restrict__ olo, int outStride)
{
    __shared__ float t[32][33];
    int n0 = blockIdx.x * 32, k0 = blockIdx.y * 32;
    int tx = threadIdx.x, ty = threadIdx.y;
    #pragma unroll
    for (int i = 0; i < 32; i += 8)
        t[ty + i][tx] = in[(size_t)(k0 + ty + i) * inRowLen + n0 + tx];
    __syncthreads();
    #pragma unroll
    for (int i = 0; i < 32; i += 8) {
        float v = t[tx][ty + i];
        bf16 h = __float2bfloat16(v);
        size_t o = (size_t)(n0 + ty + i) * outStride + k0 + tx;
        ohi[o] = h;
        olo[o] = __float2bfloat16(v - __bfloat162float(h));
    }
}

// per-batch bf16 transpose of the V part of packed qkv:
// in[(b*512+l)*3072 + 2048 + c] -> out[(b*1024+c)*512 + l];  z: b*2 + (hi/lo)
__global__ void transpose_v(const bf16* __restrict__ inh, const bf16* __restrict__ inl,
                            bf16* __restrict__ outh, bf16* __restrict__ outl)
{
    __shared__ bf16 t[32][33];
    int b = blockIdx.z >> 1, sel = blockIdx.z & 1;
    const bf16* in = sel ? inl : inh;
    bf16* out = sel ? outl : outh;
    int c0 = blockIdx.x * 32, l0 = blockIdx.y * 32;
    int tx = threadIdx.x, ty = threadIdx.y;
    #pragma unroll
    for (int i = 0; i < 32; i += 8)
        t[ty + i][tx] = in[((size_t)(b * 512 + l0 + ty + i)) * 3072 + 2048 + c0 + tx];
    __syncthreads();
    #pragma unroll
    for (int i = 0; i < 32; i += 8)
        out[((size_t)(b * 1024 + c0 + ty + i)) * 512 + l0 + tx] = t[tx][ty + i];
}

// ---------------- mma.sync GEMM (128x128 tile) -------------------------------
// EPI 1: Cf = acc+res (Wo)
// EPI 2: split(relu(acc+bias)) (conv1)
// EPI 5: Cf = acc+bias+res; prev = Cf*uw + prev*(1-uw)  (conv2 + prev_update)
// EPI 6: split(acc * (col<1024 ? 0.125 : 1))  (fused QKV)
#define TSTR    40
#define TBYTES  (128*TSTR*2)       /* 10240 */
#define STAGE_B (4*TBYTES)         /* 40960 */
#define SMEM_SZ (2*STAGE_B)        /* 81920 */

__device__ __forceinline__ void ld_plain(const bf16* __restrict__ src, int row0, int K,
                                         int k0, uint32_t sbase, int tid)
{
    #pragma unroll
    for (int i = 0; i < 2; i++) {
        int unit = i * 256 + tid;
        int row = unit >> 2, ch = unit & 3;
        cpa16(sbase + row * (TSTR*2) + ch * 16,
              src + (size_t)(row0 + row) * K + k0 + ch * 8, 16);
    }
}

template<int DSHIFT>
__device__ __forceinline__ void ld_conv(const bf16* __restrict__ src, int bm,
                                        int k0, uint32_t sbase, int tid)
{
    int w  = k0 >> DSHIFT;
    int cb = k0 & ((1 << DSHIFT) - 1);
    #pragma unroll
    for (int i = 0; i < 2; i++) {
        int unit = i * 256 + tid;
        int row = unit >> 2, ch = unit & 3;
        int r = bm + row;
        int b = r >> 9;
        int l = (r & 511) + w - 1;
        int ok = ((unsigned)l < 512u);
        int lc = ok ? l : 0;
        cpa16(sbase + row * (TSTR*2) + ch * 16,
              src + (((size_t)(b * 512 + lc)) << DSHIFT) + cb + ch * 8, ok ? 16 : 0);
    }
}

template<int CONV, int DSHIFT, int EPI>
__global__ __launch_bounds__(256, 2)
void mm_gemm(const bf16* __restrict__ Ahi, const bf16* __restrict__ Alo,
             const bf16* __restrict__ Bhi, const bf16* __restrict__ Blo,
             float* __restrict__ Cf, bf16* __restrict__ Chi, bf16* __restrict__ Clo,
             const float* __restrict__ res, const float* __restrict__ bias,
             const float* __restrict__ uw, float* __restrict__ prevp,
             int Nglob, int K)
{
    extern __shared__ char smem[];
    uint32_t sb = smem_u32(smem);
    int tid = threadIdx.x, wid = tid >> 5, lane = tid & 31;
    int bm = blockIdx.y * 128, bn = blockIdx.x * 128;
    int wm = wid & 3, wn = wid >> 2;

    float acc[2][8][4];
    #pragma unroll
    for (int mt = 0; mt < 2; mt++)
        #pragma unroll
        for (int nt = 0; nt < 8; nt++)
            #pragma unroll
            for (int j = 0; j < 4; j++) acc[mt][nt][j] = 0.f;

    int nch = K >> 5;

    // prefetch stage 0
    {
        uint32_t s = sb;
        if (CONV) { ld_conv<DSHIFT>(Ahi, bm, 0, s, tid); ld_conv<DSHIFT>(Alo, bm, 0, s + TBYTES, tid); }
        else      { ld_plain(Ahi, bm, K, 0, s, tid);      ld_plain(Alo, bm, K, 0, s + TBYTES, tid); }
        ld_plain(Bhi, bn, K, 0, s + 2*TBYTES, tid);
        ld_plain(Blo, bn, K, 0, s + 3*TBYTES, tid);
        asm volatile("cp.async.commit_group;");
    }

    // single-barrier double-buffered mainloop:
    // top-of-loop barrier proves compute(i-1) done -> stage (i+1)&1 reusable
    for (int i = 0; i < nch; i++) {
        asm volatile("cp.async.wait_group 0;");
        __syncthreads();
        if (i + 1 < nch) {
            uint32_t s2 = sb + ((i + 1) & 1) * STAGE_B;
            int k0 = (i + 1) << 5;
            if (CONV) { ld_conv<DSHIFT>(Ahi, bm, k0, s2, tid); ld_conv<DSHIFT>(Alo, bm, k0, s2 + TBYTES, tid); }
            else      { ld_plain(Ahi, bm, K, k0, s2, tid);      ld_plain(Alo, bm, K, k0, s2 + TBYTES, tid); }
            ld_plain(Bhi, bn, K, k0, s2 + 2*TBYTES, tid);
            ld_plain(Blo, bn, K, k0, s2 + 3*TBYTES, tid);
            asm volatile("cp.async.commit_group;");
        }

        uint32_t s = sb + (i & 1) * STAGE_B;
        #pragma unroll
        for (int ks = 0; ks < 2; ks++) {
            uint32_t ah[2][4], al[2][4];
            #pragma unroll
            for (int mt = 0; mt < 2; mt++) {
                uint32_t ra = s + (uint32_t)((wm*32 + mt*16) + (lane & 15)) * (TSTR*2)
                            + ks * 32 + (lane >> 4) * 16;
                ldm4(ah[mt], ra);
                ldm4(al[mt], ra + TBYTES);
            }
            uint32_t bh[4][4], bl[4][4];
            #pragma unroll
            for (int g = 0; g < 4; g++) {
                uint32_t rb = s + 2*TBYTES + (uint32_t)((wn*64 + g*16) + (lane & 15)) * (TSTR*2)
                            + ks * 32 + (lane >> 4) * 16;
                ldm4(bh[g], rb);
                ldm4(bl[g], rb + TBYTES);
            }
            #pragma unroll
            for (int mt = 0; mt < 2; mt++)
                #pragma unroll
                for (int nt = 0; nt < 8; nt++) {
                    int g = nt >> 1, o = nt & 1;
                    mma16816(acc[mt][nt], ah[mt], bh[g][o], bh[g][o + 2]);
                    mma16816(acc[mt][nt], ah[mt], bl[g][o], bl[g][o + 2]);
                    mma16816(acc[mt][nt], al[mt], bh[g][o], bh[g][o + 2]);
                }
        }
    }

    #pragma unroll
    for (int mt = 0; mt < 2; mt++)
        #pragma unroll
        for (int nt = 0; nt < 8; nt++)
            #pragma unroll
            for (int half = 0; half < 2; half++) {
                int row = bm + wm*32 + mt*16 + (lane >> 2) + half*8;
                int col = bn + wn*64 + nt*8 + (lane & 3)*2;
                float v0 = acc[mt][nt][half*2 + 0];
                float v1 = acc[mt][nt][half*2 + 1];
                size_t o = (size_t)row * Nglob + col;
                if (EPI == 1) {
                    float2 rr = *(const float2*)(res + o);
                    *(float2*)(Cf + o) = make_float2(v0 + rr.x, v1 + rr.y);
                } else if (EPI == 2) {
                    float2 bb = *(const float2*)(bias + col);
                    v0 = fmaxf(v0 + bb.x, 0.f);
                    v1 = fmaxf(v1 + bb.y, 0.f);
                    split2(v0, v1, Chi, Clo, o);
                } else if (EPI == 5) {
                    float2 rr = *(const float2*)(res + o);
                    float2 bb = *(const float2*)(bias + col);
                    float s0 = v0 + bb.x + rr.x;
                    float s1 = v1 + bb.y + rr.y;
                    *(float2*)(Cf + o) = make_float2(s0, s1);
                    float u = uw[row];
                    float2 pv = *(const float2*)(prevp + o);
                    *(float2*)(prevp + o) = make_float2(s0 * u + pv.x * (1.f - u),
                                                        s1 * u + pv.y * (1.f - u));
                } else {  // EPI 6: fused QKV split, q-scale on first 1024 cols
                    float a = (col < 1024) ? 0.125f : 1.0f;
                    split2(v0 * a, v1 * a, Chi, Clo, o);
                }
            }
}

// ---------------- attention: logits = q@k^T (per bh), K=64 --------------------
#define QSTR 72
#define QTB  (128*QSTR*2)   /* 18432 */
#define QSMEM (4*QTB)       /* 73728 */

__global__ __launch_bounds__(256, 2)
void attn_qk(const bf16* __restrict__ qkvh, const bf16* __restrict__ qkvl,
             float* __restrict__ att)
{
    extern __shared__ char smem[];
    uint32_t sb = smem_u32(smem);
    int tid = threadIdx.x, wid = tid >> 5, lane = tid & 31;
    int bz = blockIdx.z;
    int b = bz >> 4, h = bz & 15;
    size_t qbase = ((size_t)(b*512 + blockIdx.y*128)) * 3072 + h*64;
    size_t kbase = ((size_t)(b*512 + blockIdx.x*128)) * 3072 + 1024 + h*64;

    #pragma unroll
    for (int i = 0; i < 4; i++) {
        int unit = i * 256 + tid;
        int row = unit >> 3, ch = unit & 7;
        uint32_t d = (uint32_t)(row * (QSTR*2) + ch * 16);
        size_t so = (size_t)row * 3072 + ch * 8;
        cpa16(sb + d,         qkvh + qbase + so, 16);
        cpa16(sb + QTB + d,   qkvl + qbase + so, 16);
        cpa16(sb + 2*QTB + d, qkvh + kbase + so, 16);
        cpa16(sb + 3*QTB + d, qkvl + kbase + so, 16);
    }
    asm volatile("cp.async.commit_group;");
    asm volatile("cp.async.wait_group 0;");
    __syncthreads();

    int wm = wid & 3, wn = wid >> 2;
    float acc[2][8][4];
    #pragma unroll
    for (int mt = 0; mt < 2; mt++)
        #pragma unroll
        for (int nt = 0; nt < 8; nt++)
            #pragma unroll
            for (int j = 0; j < 4; j++) acc[mt][nt][j] = 0.f;

    #pragma unroll
    for (int ks = 0; ks < 4; ks++) {
        uint32_t ah[2][4], al[2][4];
        #pragma unroll
        for (int mt = 0; mt < 2; mt++) {
            uint32_t ra = sb + (uint32_t)((wm*32 + mt*16) + (lane & 15)) * (QSTR*2)
                        + ks * 32 + (lane >> 4) * 16;
            ldm4(ah[mt], ra);
            ldm4(al[mt], ra + QTB);
        }
        uint32_t bh[4][4], bl[4][4];
        #pragma unroll
        for (int g = 0; g < 4; g++) {
            uint32_t rb = sb + 2*QTB + (uint32_t)((wn*64 + g*16) + (lane & 15)) * (QSTR*2)
                        + ks * 32 + (lane >> 4) * 16;
            ldm4(bh[g], rb);
            ldm4(bl[g], rb + QTB);
        }
        #pragma unroll
        for (int mt = 0; mt < 2; mt++)
            #pragma unroll
            for (int nt = 0; nt < 8; nt++) {
                int g = nt >> 1, o = nt & 1;
                mma16816(acc[mt][nt], ah[mt], bh[g][o], bh[g][o + 2]);
                mma16816(acc[mt][nt], ah[mt], bl[g][o], bl[g][o + 2]);
                mma16816(acc[mt][nt], al[mt], bh[g][o], bh[g][o + 2]);
            }
    }

    #pragma unroll
    for (int mt = 0; mt < 2; mt++)
        #pragma unroll
        for (int nt = 0; nt < 8; nt++)
            #pragma unroll
            for (int half = 0; half < 2; half++) {
                int rloc = wm*32 + mt*16 + (lane >> 2) + half*8;
                int cloc = wn*64 + nt*8 + (lane & 3)*2;
                float* ap = att + ((size_t)bz*512 + blockIdx.y*128 + rloc)*512
                          + blockIdx.x*128 + cloc;
                *(float2*)ap = make_float2(acc[mt][nt][half*2], acc[mt][nt][half*2 + 1]);
            }
}

// ---------------- attention: ctx = w@v (per bh), tile 128x64, K=512 -----------
#define WA_B  (128*TSTR*2)   /* 10240 */
#define WB_B  (64*TSTR*2)    /* 5120 */
#define WSTAGE (2*WA_B + 2*WB_B)   /* 30720 */
#define WSMEM (2*WSTAGE)           /* 61440 */

__global__ __launch_bounds__(256, 2)
void attn_wv(const bf16* __restrict__ wh, const bf16* __restrict__ wl,
             const bf16* __restrict__ vth, const bf16* __restrict__ vtl,
             bf16* __restrict__ ctxh, bf16* __restrict__ ctxl)
{
    extern __shared__ char smem[];
    uint32_t sb = smem_u32(smem);
    int tid = threadIdx.x, wid = tid >> 5, lane = tid & 31;
    int bz = blockIdx.y;
    int b = bz >> 4, h = bz & 15;
    size_t abase = (size_t)bz*262144 + (size_t)blockIdx.x*65536;
    size_t bbase = (size_t)bz*32768;
    int wm = wid & 3, wn = wid >> 2;

    float acc[2][4][4];
    #pragma unroll
    for (int mt = 0; mt < 2; mt++)
        #pragma unroll
        for (int nt = 0; nt < 4; nt++)
            #pragma unroll
            for (int j = 0; j < 4; j++) acc[mt][nt][j] = 0.f;

    auto load_chunk = [&](int k0, uint32_t s) {
        #pragma unroll
        for (int i = 0; i < 2; i++) {
            int unit = i * 256 + tid;
            int row = unit >> 2, ch = unit & 3;
            uint32_t d = (uint32_t)(row * (TSTR*2) + ch * 16);
            size_t so = abase + (size_t)row * 512 + k0 + ch * 8;
            cpa16(s + d,        wh + so, 16);
            cpa16(s + WA_B + d, wl + so, 16);
        }
        {
            int row = tid >> 2, ch = tid & 3;
            uint32_t d = (uint32_t)(row * (TSTR*2) + ch * 16);
            size_t so = bbase + (size_t)row * 512 + k0 + ch * 8;
            cpa16(s + 2*WA_B + d,        vth + so, 16);
            cpa16(s + 2*WA_B + WB_B + d, vtl + so, 16);
        }
    };

    load_chunk(0, sb);
    asm volatile("cp.async.commit_group;");

    for (int i = 0; i < 16; i++) {
        asm volatile("cp.async.wait_group 0;");
        __syncthreads();
        if (i + 1 < 16) {
            load_chunk((i + 1) << 5, sb + ((i + 1) & 1) * WSTAGE);
            asm volatile("cp.async.commit_group;");
        }

        uint32_t s = sb + (i & 1) * WSTAGE;
        #pragma unroll
        for (int ks = 0; ks < 2; ks++) {
            uint32_t ah[2][4], al[2][4];
            #pragma unroll
            for (int mt = 0; mt < 2; mt++) {
                uint32_t ra = s + (uint32_t)((wm*32 + mt*16) + (lane & 15)) * (TSTR*2)
                            + ks * 32 + (lane >> 4) * 16;
                ldm4(ah[mt], ra);
                ldm4(al[mt], ra + WA_B);
            }
            uint32_t bh[2][4], bl[2][4];
            #pragma unroll
            for (int g = 0; g < 2; g++) {
                uint32_t rb = s + 2*WA_B + (uint32_t)((wn*32 + g*16) + (lane & 15)) * (TSTR*2)
                            + ks * 32 + (lane >> 4) * 16;
                ldm4(bh[g], rb);
                ldm4(bl[g], rb + WB_B);
            }
            #pragma unroll
            for (int mt = 0; mt < 2; mt++)
                #pragma unroll
                for (int nt = 0; nt < 4; nt++) {
                    int g = nt >> 1, o = nt & 1;
                    mma16816(acc[mt][nt], ah[mt], bh[g][o], bh[g][o + 2]);
                    mma16816(acc[mt][nt], ah[mt], bl[g][o], bl[g][o + 2]);
                    mma16816(acc[mt][nt], al[mt], bh[g][o], bh[g][o + 2]);
                }
        }
    }

    #pragma unroll
    for (int mt = 0; mt < 2; mt++)
        #pragma unroll
        for (int nt = 0; nt < 4; nt++)
            #pragma unroll
            for (int half = 0; half < 2; half++) {
                int rloc = wm*32 + mt*16 + (lane >> 2) + half*8;
                int row = b*512 + blockIdx.x*128 + rloc;
                int col = h*64 + wn*32 + nt*8 + (lane & 3)*2;
                size_t o = (size_t)row * 1024 + col;
                split2(acc[mt][nt][half*2], acc[mt][nt][half*2 + 1], ctxh, ctxl, o);
            }
}

// ---------------- softmax + bf16 split ----------------------------------------
__global__ void softmax_split(const float* __restrict__ att,
                              bf16* __restrict__ wh, bf16* __restrict__ wl)
{
    int row  = blockIdx.x * 8 + (threadIdx.x >> 5);
    int lane = threadIdx.x & 31;
    const float* x = att + (size_t)row * 512;
    float v[16];
    float m = -1e30f;
    #pragma unroll
    for (int i = 0; i < 16; i++) { v[i] = x[lane + 32*i]; m = fmaxf(m, v[i]); }
    #pragma unroll
    for (int o = 16; o; o >>= 1) m = fmaxf(m, __shfl_xor_sync(0xffffffffu, m, o));
    float s = 0.f;
    #pragma unroll
    for (int i = 0; i < 16; i++) { v[i] = expf(v[i] - m); s += v[i]; }
    #pragma unroll
    for (int o = 16; o; o >>= 1) s += __shfl_xor_sync(0xffffffffu, s, o);
    float inv = 1.f / s;
    #pragma unroll
    for (int i = 0; i < 16; i++) {
        float w = v[i] * inv;
        bf16 hh = __float2bfloat16(w);
        size_t o = (size_t)row * 512 + lane + 32*i;
        wh[o] = hh;
        wl[o] = __float2bfloat16(w - __bfloat162float(hh));
    }
}

// ---------------- fused: time/pos add + ACT halt + layernorm1 -----------------
__global__ __launch_bounds__(256) void pre_layer(
    int t, const float* __restrict__ p_w, const float* __restrict__ p_b,
    const float* __restrict__ g, const float* __restrict__ bgm)
{
    __shared__ float sh1[8], sh2[8], sh3[8];
    const float NEG_LOG_INC = -0.018024149455921103f;
    int row = blockIdx.x;
    int l   = row & 511;
    int tid = threadIdx.x;
    float* x = g_state + (size_t)row * 1024;
    float v[4];
    float sum = 0.f, dot = 0.f;
    #pragma unroll
    for (int j = 0; j < 4; j++) {
        int d = tid + 256*j;
        int i = d & 511;
        float invt = expf((float)i * NEG_LOG_INC);
        float a1 = (float)l * invt;
        float a2 = (float)t * invt;
        float sig = (d < 512) ? (sinf(a1) + sinf(a2)) : (cosf(a1) + cosf(a2));
        float val = x[d] + sig;
        x[d] = val;
        v[j] = val;
        sum += val;
        dot += val * p_w[d];
    }
    #pragma unroll
    for (int o = 16; o; o >>= 1) {
        sum += __shfl_xor_sync(0xffffffffu, sum, o);
        dot += __shfl_xor_sync(0xffffffffu, dot, o);
    }
    if ((tid & 31) == 0) { sh1[tid >> 5] = sum; sh3[tid >> 5] = dot; }
    __syncthreads();
    float tot = 0.f, dtot = 0.f;
    #pragma unroll
    for (int w = 0; w < 8; w++) { tot += sh1[w]; dtot += sh3[w]; }
    float mu = tot * (1.f / 1024.f);
    float q = 0.f;
    #pragma unroll
    for (int j = 0; j < 4; j++) { float d = v[j] - mu; q += d * d; }
    #pragma unroll
    for (int o = 16; o; o >>= 1) q += __shfl_xor_sync(0xffffffffu, q, o);
    if ((tid & 31) == 0) sh2[tid >> 5] = q;
    __syncthreads();

    if (tid == 0) {
        float p   = 1.f / (1.f + expf(-(dtot + p_b[0])));
        float hp  = g_hp[row], rem = g_rem[row], nup = g_nup[row];
        float still = (hp < 1.0f) ? 1.f : 0.f;
        float add   = hp + p * still;
        float nh    = ((add > 0.9f) ? 1.f : 0.f) * still;
        still       = ((add <= 0.9f) ? 1.f : 0.f) * still;
        hp  += p * still;
        rem += nh * (1.f - hp);
        hp  += nh * rem;
        nup += still + nh;
        g_hp[row] = hp; g_rem[row] = rem; g_nup[row] = nup;
        g_uw[row] = p * still + nh * rem;
    }

    float qt = 0.f;
    #pragma unroll
    for (int w = 0; w < 8; w++) qt += sh2[w];
    float sd  = sqrtf(qt / 1023.f);
    float inv = 1.f / (sd + 1e-6f);
    #pragma unroll
    for (int j = 0; j < 4; j++) {
        int d = tid + 256*j;
        float y = g[d] * (v[j] - mu) * inv + bgm[d];
        bf16 h = __float2bfloat16(y);
        size_t o = (size_t)row * 1024 + d;
        g_xnh[o] = h;
        g_xnl[o] = __float2bfloat16(y - __bfloat162float(h));
    }
}

// ---------------- misc elementwise --------------------------------------------
__global__ void embed_init(const int* __restrict__ X, const float* __restrict__ emb) {
    int idx = blockIdx.x * 256 + threadIdx.x;
    int row = idx >> 10;
    int d   = idx & 1023;
    g_state[idx] = emb[(size_t)X[row] * 1024 + d];
    g_prev[idx]  = 0.f;
}

__global__ void zero_act() {
    int i = blockIdx.x * 256 + threadIdx.x;
    if (i < ROWS_) { g_hp[i] = 0.f; g_rem[i] = 0.f; g_nup[i] = 0.f; }
}

// layernorm (fp32 in) -> bf16 hi/lo split outputs  (ln2)
__global__ __launch_bounds__(256) void layernorm_k(
    const float* __restrict__ in, bf16* __restrict__ ohi, bf16* __restrict__ olo,
    const float* __restrict__ g, const float* __restrict__ b)
{
    __shared__ float sh1[8], sh2[8];
    int row = blockIdx.x;
    int tid = threadIdx.x;
    const float* x = in + (size_t)row * 1024;
    float v[4];
    #pragma unroll
    for (int j = 0; j < 4; j++) v[j] = x[tid + 256*j];
    float s = v[0] + v[1] + v[2] + v[3];
    #pragma unroll
    for (int o = 16; o; o >>= 1) s += __shfl_xor_sync(0xffffffffu, s, o);
    if ((tid & 31) == 0) sh1[tid >> 5] = s;
    __syncthreads();
    float tot = 0.f;
    #pragma unroll
    for (int w = 0; w < 8; w++) tot += sh1[w];
    float mu = tot * (1.f / 1024.f);
    float q = 0.f;
    #pragma unroll
    for (int j = 0; j < 4; j++) { float d = v[j] - mu; q += d * d; }
    #pragma unroll
    for (int o = 16; o; o >>= 1) q += __shfl_xor_sync(0xffffffffu, q, o);
    if ((tid & 31) == 0) sh2[tid >> 5] = q;
    __syncthreads();
    float qt = 0.f;
    #pragma unroll
    for (int w = 0; w < 8; w++) qt += sh2[w];
    float sd  = sqrtf(qt / 1023.f);
    float inv = 1.f / (sd + 1e-6f);
    #pragma unroll
    for (int j = 0; j < 4; j++) {
        int d = tid + 256*j;
        float y = g[d] * (v[j] - mu) * inv + b[d];
        bf16 h = __float2bfloat16(y);
        size_t o = (size_t)row * 1024 + d;
        ohi[o] = h;
        olo[o] = __float2bfloat16(y - __bfloat162float(h));
    }
}

// ---------------- head --------------------------------------------------------
__global__ __launch_bounds__(256) void head_out(
    const float* __restrict__ W_out, const float* __restrict__ b_out, float* __restrict__ out)
{
    __shared__ float sh[4][256];
    int b = blockIdx.x;
    int tid = threadIdx.x;
    float sum[4] = {0.f, 0.f, 0.f, 0.f};
    for (int l = 0; l < 512; l++) {
        const float* p = g_prev + ((size_t)(b*512 + l)) * 1024;
        #pragma unroll
        for (int j = 0; j < 4; j++) sum[j] += p[tid + 256*j];
    }
    float part[4] = {0.f, 0.f, 0.f, 0.f};
    #pragma unroll
    for (int j = 0; j < 4; j++) {
        int d = tid + 256*j;
        float m = sum[j] * (1.f / 512.f);
        #pragma unroll
        for (int o = 0; o < 4; o++) part[o] += m * W_out[d*4 + o];
    }
    #pragma unroll
    for (int o = 0; o < 4; o++) sh[o][tid] = part[o];
    __syncthreads();
    for (int s = 128; s > 0; s >>= 1) {
        if (tid < s)
            #pragma unroll
            for (int o = 0; o < 4; o++) sh[o][tid] += sh[o][tid + s];
        __syncthreads();
    }
    if (tid == 0) {
        float a[4];
        #pragma unroll
        for (int o = 0; o < 4; o++) { a[o] = sh[o][0] + b_out[o]; out[b*4 + o] = a[o]; }
        float mx = fmaxf(fmaxf(a[0], a[1]), fmaxf(a[2], a[3]));
        float e[4], s = 0.f;
        #pragma unroll
        for (int o = 0; o < 4; o++) { e[o] = expf(a[o] - mx); s += e[o]; }
        #pragma unroll
        for (int o = 0; o < 4; o++) out[32 + b*4 + o] = e[o] / s;
    }
}

__global__ void tail_out(float* __restrict__ out) {
    int i = blockIdx.x * 256 + threadIdx.x;
    out[64 + i]        = g_rem[i];
    out[64 + 4096 + i] = g_nup[i];
}

// ---------------- launcher ----------------------------------------------------
extern "C" void kernel_launch(void* const* d_in, const int* in_sizes, int n_in,
                              void* d_out, int out_size) {
    const int*   X     = (const int*)  d_in[0];
    const float* emb   = (const float*)d_in[1];
    const float* p_w   = (const float*)d_in[2];
    const float* p_b   = (const float*)d_in[3];
    const float* Wq    = (const float*)d_in[4];
    const float* Wk    = (const float*)d_in[5];
    const float* Wv    = (const float*)d_in[6];
    const float* Wo    = (const float*)d_in[7];
    const float* ln1_g = (const float*)d_in[8];
    const float* ln1_b = (const float*)d_in[9];
    const float* ln2_g = (const float*)d_in[10];
    const float* ln2_b = (const float*)d_in[11];
    const float* K1    = (const float*)d_in[12];
    const float* c1_b  = (const float*)d_in[13];
    const float* K2    = (const float*)d_in[14];
    const float* c2_b  = (const float*)d_in[15];
    const float* W_out = (const float*)d_in[16];
    const float* b_out = (const float*)d_in[17];
    float* out = (float*)d_out;

    float *state, *att, *prevp, *uw;
    bf16 *xnh, *xnl, *qkvh, *qkvl, *vth, *vtl, *ctxh, *ctxl, *wh, *wl, *hh, *hl;
    bf16 *Wqkvh, *Wqkvl, *Woh, *Wol, *K1h, *K1l, *K2h, *K2l;
    cudaGetSymbolAddress((void**)&state, g_state);
    cudaGetSymbolAddress((void**)&prevp, g_prev);
    cudaGetSymbolAddress((void**)&uw,    g_uw);
    cudaGetSymbolAddress((void**)&att,   g_att);
    cudaGetSymbolAddress((void**)&xnh,   g_xnh);   cudaGetSymbolAddress((void**)&xnl,  g_xnl);
    cudaGetSymbolAddress((void**)&qkvh,  g_qkvh);  cudaGetSymbolAddress((void**)&qkvl, g_qkvl);
    cudaGetSymbolAddress((void**)&vth,   g_vth);   cudaGetSymbolAddress((void**)&vtl,  g_vtl);
    cudaGetSymbolAddress((void**)&ctxh,  g_ctxh);  cudaGetSymbolAddress((void**)&ctxl, g_ctxl);
    cudaGetSymbolAddress((void**)&wh,    g_wh);    cudaGetSymbolAddress((void**)&wl,   g_wl);
    cudaGetSymbolAddress((void**)&hh,    g_hh);    cudaGetSymbolAddress((void**)&hl,   g_hl);
    cudaGetSymbolAddress((void**)&Wqkvh, g_Wqkvh); cudaGetSymbolAddress((void**)&Wqkvl,g_Wqkvl);
    cudaGetSymbolAddress((void**)&Woh,   g_Woh);   cudaGetSymbolAddress((void**)&Wol,  g_Wol);
    cudaGetSymbolAddress((void**)&K1h,   g_K1h);   cudaGetSymbolAddress((void**)&K1l,  g_K1l);
    cudaGetSymbolAddress((void**)&K2h,   g_K2h);   cudaGetSymbolAddress((void**)&K2l,  g_K2l);

    cudaFuncSetAttribute(mm_gemm<0,0,1>,  cudaFuncAttributeMaxDynamicSharedMemorySize, SMEM_SZ);
    cudaFuncSetAttribute(mm_gemm<0,0,6>,  cudaFuncAttributeMaxDynamicSharedMemorySize, SMEM_SZ);
    cudaFuncSetAttribute(mm_gemm<1,10,2>, cudaFuncAttributeMaxDynamicSharedMemorySize, SMEM_SZ);
    cudaFuncSetAttribute(mm_gemm<1,12,5>, cudaFuncAttributeMaxDynamicSharedMemorySize, SMEM_SZ);
    cudaFuncSetAttribute(attn_qk, cudaFuncAttributeMaxDynamicSharedMemorySize, QSMEM);
    cudaFuncSetAttribute(attn_wv, cudaFuncAttributeMaxDynamicSharedMemorySize, WSMEM);

    dim3 tb(32, 8);
    // packed QKV weights: rows 0-1023 = Wq^T, 1024-2047 = Wk^T, 2048-3071 = Wv^T
    transpose_split<<<dim3(32, 32), tb>>>(Wq, 1024, Wqkvh,              Wqkvl,              1024);
    transpose_split<<<dim3(32, 32), tb>>>(Wk, 1024, Wqkvh + 1024*1024,  Wqkvl + 1024*1024,  1024);
    transpose_split<<<dim3(32, 32), tb>>>(Wv, 1024, Wqkvh + 2048*1024,  Wqkvl + 2048*1024,  1024);
    transpose_split<<<dim3(32, 32), tb>>>(Wo, 1024, Woh, Wol, 1024);
    for (int w = 0; w < 3; w++) {
        transpose_split<<<dim3(128, 32), tb>>>(K1 + (size_t)w*D_*F_, F_, K1h + w*D_, K1l + w*D_, 3*D_);
        transpose_split<<<dim3(32, 128), tb>>>(K2 + (size_t)w*F_*D_, D_, K2h + w*F_, K2l + w*F_, 3*F_);
    }

    embed_init<<<NST_/256, 256>>>(X, emb);
    zero_act<<<16, 256>>>();

    for (int t = 0; t < NL_; t++) {
        pre_layer<<<ROWS_, 256>>>(t, p_w, p_b, ln1_g, ln1_b);

        // fused QKV: N=3072
        mm_gemm<0,0,6><<<dim3(24, 32), 256, SMEM_SZ>>>(xnh, xnl, Wqkvh, Wqkvl,
            nullptr, qkvh, qkvl, nullptr, nullptr, nullptr, nullptr, 3*D_, D_);

        transpose_v<<<dim3(32, 16, 16), tb>>>(qkvh, qkvl, vth, vtl);

        attn_qk<<<dim3(4, 4, B_*H_), 256, QSMEM>>>(qkvh, qkvl, att);
        softmax_split<<<(B_*H_*L_)/8, 256>>>(att, wh, wl);
        attn_wv<<<dim3(4, B_*H_), 256, WSMEM>>>(wh, wl, vth, vtl, ctxh, ctxl);

        dim3 gp(D_/128, ROWS_/128);
        mm_gemm<0,0,1><<<gp, 256, SMEM_SZ>>>(ctxh, ctxl, Woh, Wol,
            state, nullptr, nullptr, state, nullptr, nullptr, nullptr, D_, D_);
        layernorm_k<<<ROWS_, 256>>>(state, xnh, xnl, ln2_g, ln2_b);

        mm_gemm<1,10,2><<<dim3(F_/128, ROWS_/128), 256, SMEM_SZ>>>(xnh, xnl, K1h, K1l,
            nullptr, hh, hl, nullptr, c1_b, nullptr, nullptr, F_, 3*D_);
        // conv2 + fused prev_update
        mm_gemm<1,12,5><<<gp, 256, SMEM_SZ>>>(hh, hl, K2h, K2l,
            state, nullptr, nullptr, state, c2_b, uw, prevp, D_, 3*F_);
    }

    head_out<<<B_, 256>>>(W_out, b_out, out);
    tail_out<<<ROWS_/256, 256>>>(out);
}